// round 3
// baseline (speedup 1.0000x reference)
#include <cuda_runtime.h>
#include <cuda_bf16.h>
#include <cstdint>
#include <math.h>

#define NB   2
#define NS   2048
#define NDIM 1024
#define NH   16
#define QD   64
#define VDm  96
#define NHV  (NH*VDm)     /* 1536 */
#define NROWS (NB*NS)     /* 4096 */

// ---------------- scratch (device globals; allocation is forbidden) ----------
__device__ float g_xn [NROWS*NDIM];
__device__ float g_q  [NROWS*NDIM];   // [row][h*64+d]
__device__ float g_k  [NROWS*QD];
__device__ float g_v  [NROWS*VDm];
__device__ float g_ctx[NROWS*NHV];

// ---------------- helpers ----------------------------------------------------
__device__ __forceinline__ uint32_t f2tf(float x){
    uint32_t u; asm("cvt.rna.tf32.f32 %0, %1;" : "=r"(u) : "f"(x)); return u;
}
__device__ __forceinline__ float f2tff(float x){ return __uint_as_float(f2tf(x)); }

__device__ __forceinline__ void mma8(float c[4], const uint32_t a[4], const uint32_t b[2]){
    asm volatile("mma.sync.aligned.m16n8k8.row.col.f32.tf32.tf32.f32 "
        "{%0,%1,%2,%3}, {%4,%5,%6,%7}, {%8,%9}, {%0,%1,%2,%3};"
        : "+f"(c[0]), "+f"(c[1]), "+f"(c[2]), "+f"(c[3])
        : "r"(a[0]), "r"(a[1]), "r"(a[2]), "r"(a[3]), "r"(b[0]), "r"(b[1]));
}

// exp(5*tanh(l/5)) / e^5  (constant e^5 cancels in the softmax normalization)
__device__ __forceinline__ float softcap_exp(float l){
    float e = __expf(0.4f * l);
    return __expf(-10.0f / (1.0f + e));
}

// ---------------- RMSNorm -----------------------------------------------------
__global__ __launch_bounds__(256) void rmsnorm_kernel(const float* __restrict__ x,
                                                      const float* __restrict__ w){
    int row = blockIdx.x;
    int t = threadIdx.x;
    float4 v = ((const float4*)(x + (size_t)row*NDIM))[t];
    float ss = v.x*v.x + v.y*v.y + v.z*v.z + v.w*v.w;
    #pragma unroll
    for (int o=16;o;o>>=1) ss += __shfl_xor_sync(0xffffffffu, ss, o);
    __shared__ float red[8];
    if ((t&31)==0) red[t>>5] = ss;
    __syncthreads();
    if (t < 32){
        float s2 = (t < 8) ? red[t] : 0.f;
        #pragma unroll
        for (int o=4;o;o>>=1) s2 += __shfl_xor_sync(0xffffffffu, s2, o);
        if (t==0) red[0] = s2;
    }
    __syncthreads();
    float scale = rsqrtf(red[0]*(1.0f/NDIM) + 1e-8f);
    float4 wv = ((const float4*)w)[t];
    float4 o;
    o.x = v.x*wv.x*scale; o.y = v.y*wv.y*scale;
    o.z = v.z*wv.z*scale; o.w = v.w*wv.w*scale;
    ((float4*)(g_xn + (size_t)row*NDIM))[t] = o;
}

// ---------------- generic tf32 GEMM: C[M,N] = A[M,K] @ W[K,N] (+bias) ---------
// BM=128, BN=64, BK=16. 256 threads = 8 warps in 4(m) x 2(n), warp tile 32x32.
__global__ __launch_bounds__(256) void gemm_tf32(
    const float* __restrict__ A, const float* __restrict__ W,
    const float* __restrict__ bias, float* __restrict__ C,
    int N, int K)
{
    __shared__ float As[128][20];
    __shared__ float Bs[16][72];
    const int tid = threadIdx.x;
    const int warp = tid>>5, lane = tid&31;
    const int gid = lane>>2, tig = lane&3;
    const int mw = warp>>1, nw = warp&1;
    const int m0 = blockIdx.y*128, n0 = blockIdx.x*64;

    float acc[2][4][4];
    #pragma unroll
    for (int i=0;i<2;i++)
        #pragma unroll
        for (int j=0;j<4;j++)
            #pragma unroll
            for (int l=0;l<4;l++) acc[i][j][l] = 0.f;

    for (int k0=0;k0<K;k0+=16){
        #pragma unroll
        for (int r=0;r<2;r++){
            int f = tid + 256*r;
            int m = f>>2, kq = (f&3)*4;
            float4 v = *(const float4*)(A + (size_t)(m0+m)*K + k0 + kq);
            v.x=f2tff(v.x); v.y=f2tff(v.y); v.z=f2tff(v.z); v.w=f2tff(v.w);
            *(float4*)&As[m][kq] = v;
        }
        {
            int kk = tid>>4, nq = (tid&15)*4;
            float4 v = make_float4(0.f,0.f,0.f,0.f);
            if (n0 + nq + 3 < N){
                v = *(const float4*)(W + (size_t)(k0+kk)*N + n0 + nq);
                v.x=f2tff(v.x); v.y=f2tff(v.y); v.z=f2tff(v.z); v.w=f2tff(v.w);
            }
            *(float4*)&Bs[kk][nq] = v;
        }
        __syncthreads();
        #pragma unroll
        for (int ks=0;ks<2;ks++){
            uint32_t a[2][4];
            #pragma unroll
            for (int mt=0;mt<2;mt++){
                int rb = mw*32 + mt*16;
                a[mt][0] = __float_as_uint(As[rb+gid  ][ks*8+tig  ]);
                a[mt][1] = __float_as_uint(As[rb+gid+8][ks*8+tig  ]);
                a[mt][2] = __float_as_uint(As[rb+gid  ][ks*8+tig+4]);
                a[mt][3] = __float_as_uint(As[rb+gid+8][ks*8+tig+4]);
            }
            #pragma unroll
            for (int nt=0;nt<4;nt++){
                uint32_t bb[2];
                int cc = nw*32 + nt*8 + gid;
                bb[0] = __float_as_uint(Bs[ks*8+tig  ][cc]);
                bb[1] = __float_as_uint(Bs[ks*8+tig+4][cc]);
                #pragma unroll
                for (int mt=0;mt<2;mt++) mma8(acc[mt][nt], a[mt], bb);
            }
        }
        __syncthreads();
    }
    #pragma unroll
    for (int mt=0;mt<2;mt++){
        #pragma unroll
        for (int nt=0;nt<4;nt++){
            int r0 = m0 + mw*32 + mt*16 + gid;
            int c0 = n0 + nw*32 + nt*8 + 2*tig;
            if (c0 + 1 < N || c0 < N){
                float b0 = bias ? bias[c0]   : 0.f;
                float b1 = bias ? bias[c0+1] : 0.f;
                C[(size_t)r0*N + c0]       = acc[mt][nt][0] + b0;
                C[(size_t)r0*N + c0+1]     = acc[mt][nt][1] + b1;
                C[(size_t)(r0+8)*N + c0]   = acc[mt][nt][2] + b0;
                C[(size_t)(r0+8)*N + c0+1] = acc[mt][nt][3] + b1;
            }
        }
    }
}

// ---------------- RoPE (in-place on g_q and g_k) ------------------------------
// One warp per (row, unit). unit 0..15 = q heads, unit 16 = k.
__global__ __launch_bounds__(256) void rope_kernel(){
    int w = threadIdx.x >> 5;
    int lane = threadIdx.x & 31;
    int g = blockIdx.x*8 + w;
    if (g >= NROWS*17) return;
    int row = g / 17;
    int unit = g % 17;
    int s = row % NS;
    float* base = (unit < 16) ? (g_q + (size_t)row*NDIM + unit*QD)
                              : (g_k + (size_t)row*QD);
    const float STEP = 0.106817095236f;   // log10(2048)/31
    float freq = exp10f(-(float)lane * STEP);
    float theta = (float)s * freq;
    float st, ct;
    sincosf(theta, &st, &ct);
    float x1 = base[2*lane];
    float x2 = base[2*lane+1];
    __syncwarp();
    base[lane]      = x1*ct - x2*st;
    base[lane + 32] = x1*st + x2*ct;
}

// ---------------- fused attention ---------------------------------------------
// Block: 64 queries for one (b,h). 128 threads = 4 warps, each owns 16 rows.
// Loop over j in chunks of 32. QK^T in 3xTF32; bias add; softcap-exp (no max
// needed); P -> smem (tf32); P@V single tf32; normalize at the end.
__global__ __launch_bounds__(128) void attn_kernel(const float* __restrict__ bias){
    __shared__ float Khi[32][68];
    __shared__ float Klo[32][68];
    __shared__ float Vs [32][104];
    __shared__ float Ps [64][36];

    const int w = threadIdx.x >> 5, lane = threadIdx.x & 31;
    const int gid = lane >> 2, tig = lane & 3;
    const int it = blockIdx.x;    // 0..31
    const int h  = blockIdx.y;    // 0..15
    const int b  = blockIdx.z;    // 0..1
    const int i0 = it*64;
    const int row0 = b*NS + i0 + w*16;

    // Q fragments (hi/lo split), loop-invariant across j-chunks
    uint32_t qhi[8][4], qlo[8][4];
    #pragma unroll
    for (int ks=0; ks<8; ks++){
        #pragma unroll
        for (int r=0;r<4;r++){
            int rr = gid + (r&1)*8;
            int cc = ks*8 + tig + (r>>1)*4;
            float x = g_q[(size_t)(row0+rr)*NDIM + h*QD + cc];
            uint32_t hi = f2tf(x);
            qhi[ks][r] = hi;
            qlo[ks][r] = f2tf(x - __uint_as_float(hi));
        }
    }

    float ctx[12][4];
    #pragma unroll
    for (int nt=0;nt<12;nt++)
        #pragma unroll
        for (int r=0;r<4;r++) ctx[nt][r] = 0.f;
    float rsum0 = 0.f, rsum1 = 0.f;

    const float* bptr = bias + (((size_t)(b*NH + h))*NS + i0)*NS;

    for (int jc=0; jc<NS/32; jc++){
        int j0 = jc*32;
        __syncthreads();   // previous chunk's smem reads done

        // load K chunk (hi/lo) : 32 x 64
        for (int u = threadIdx.x; u < 32*16; u += 128){
            int jj = u >> 4, c4 = (u & 15)*4;
            float4 v = *(const float4*)(g_k + (size_t)(b*NS + j0 + jj)*QD + c4);
            float h0=f2tff(v.x), h1=f2tff(v.y), h2=f2tff(v.z), h3=f2tff(v.w);
            Khi[jj][c4]=h0; Khi[jj][c4+1]=h1; Khi[jj][c4+2]=h2; Khi[jj][c4+3]=h3;
            Klo[jj][c4]  =f2tff(v.x-h0); Klo[jj][c4+1]=f2tff(v.y-h1);
            Klo[jj][c4+2]=f2tff(v.z-h2); Klo[jj][c4+3]=f2tff(v.w-h3);
        }
        // load V chunk : 32 x 96
        for (int u = threadIdx.x; u < 32*24; u += 128){
            int jj = u / 24, c4 = (u % 24)*4;
            float4 v = *(const float4*)(g_v + (size_t)(b*NS + j0 + jj)*VDm + c4);
            Vs[jj][c4]=f2tff(v.x); Vs[jj][c4+1]=f2tff(v.y);
            Vs[jj][c4+2]=f2tff(v.z); Vs[jj][c4+3]=f2tff(v.w);
        }
        __syncthreads();

        // S = Q @ K^T (16 x 32 per warp), 3xTF32
        float s[4][4];
        #pragma unroll
        for (int nt=0;nt<4;nt++)
            #pragma unroll
            for (int r=0;r<4;r++) s[nt][r]=0.f;
        #pragma unroll
        for (int ks=0;ks<8;ks++){
            #pragma unroll
            for (int nt=0;nt<4;nt++){
                int jj = nt*8 + gid;
                uint32_t bhi[2], blo[2];
                bhi[0] = __float_as_uint(Khi[jj][ks*8+tig  ]);
                bhi[1] = __float_as_uint(Khi[jj][ks*8+tig+4]);
                blo[0] = __float_as_uint(Klo[jj][ks*8+tig  ]);
                blo[1] = __float_as_uint(Klo[jj][ks*8+tig+4]);
                mma8(s[nt], qhi[ks], bhi);
                mma8(s[nt], qhi[ks], blo);
                mma8(s[nt], qlo[ks], bhi);
            }
        }

        // bias + softcap-exp + row-sum + stage P
        int pr = w*16 + gid;
        #pragma unroll
        for (int nt=0;nt<4;nt++){
            int jl = nt*8 + 2*tig;
            const float* bp0 = bptr + (size_t)(w*16+gid)*NS + j0 + jl;
            float2 b0 = *(const float2*)bp0;
            float2 b1 = *(const float2*)(bp0 + (size_t)8*NS);
            float p00 = softcap_exp(s[nt][0] + b0.x);
            float p01 = softcap_exp(s[nt][1] + b0.y);
            float p10 = softcap_exp(s[nt][2] + b1.x);
            float p11 = softcap_exp(s[nt][3] + b1.y);
            rsum0 += p00 + p01;
            rsum1 += p10 + p11;
            Ps[pr  ][jl] = f2tff(p00);  Ps[pr  ][jl+1] = f2tff(p01);
            Ps[pr+8][jl] = f2tff(p10);  Ps[pr+8][jl+1] = f2tff(p11);
        }
        __syncwarp();

        // ctx += P @ V  (16 x 96 per warp)
        #pragma unroll
        for (int ks=0;ks<4;ks++){
            uint32_t pa[4];
            pa[0] = __float_as_uint(Ps[pr  ][ks*8+tig  ]);
            pa[1] = __float_as_uint(Ps[pr+8][ks*8+tig  ]);
            pa[2] = __float_as_uint(Ps[pr  ][ks*8+tig+4]);
            pa[3] = __float_as_uint(Ps[pr+8][ks*8+tig+4]);
            #pragma unroll
            for (int nt=0;nt<12;nt++){
                uint32_t vb[2];
                vb[0] = __float_as_uint(Vs[ks*8+tig  ][nt*8+gid]);
                vb[1] = __float_as_uint(Vs[ks*8+tig+4][nt*8+gid]);
                mma8(ctx[nt], pa, vb);
            }
        }
        __syncwarp();
    }

    // reduce row sums across the quad (tig lanes)
    rsum0 += __shfl_xor_sync(0xffffffffu, rsum0, 1);
    rsum0 += __shfl_xor_sync(0xffffffffu, rsum0, 2);
    rsum1 += __shfl_xor_sync(0xffffffffu, rsum1, 1);
    rsum1 += __shfl_xor_sync(0xffffffffu, rsum1, 2);
    float inv0 = 1.f / rsum0, inv1 = 1.f / rsum1;

    int orow = b*NS + i0 + w*16 + gid;
    #pragma unroll
    for (int nt=0;nt<12;nt++){
        int col = h*VDm + nt*8 + 2*tig;
        g_ctx[(size_t)orow*NHV + col]       = ctx[nt][0]*inv0;
        g_ctx[(size_t)orow*NHV + col+1]     = ctx[nt][1]*inv0;
        g_ctx[(size_t)(orow+8)*NHV + col]   = ctx[nt][2]*inv1;
        g_ctx[(size_t)(orow+8)*NHV + col+1] = ctx[nt][3]*inv1;
    }
}

// ---------------- launch --------------------------------------------------------
extern "C" void kernel_launch(void* const* d_in, const int* in_sizes, int n_in,
                              void* d_out, int out_size) {
    const float* x    = (const float*)d_in[0];
    const float* ab   = (const float*)d_in[1];
    const float* rmsw = (const float*)d_in[2];
    const float* Wq   = (const float*)d_in[3];
    const float* Wk   = (const float*)d_in[4];
    const float* Wv   = (const float*)d_in[5];
    const float* bv   = (const float*)d_in[6];
    const float* Wo   = (const float*)d_in[7];
    const float* bo   = (const float*)d_in[8];
    float* out = (float*)d_out;

    float *xn, *q, *k, *v, *ctx;
    cudaGetSymbolAddress((void**)&xn,  g_xn);
    cudaGetSymbolAddress((void**)&q,   g_q);
    cudaGetSymbolAddress((void**)&k,   g_k);
    cudaGetSymbolAddress((void**)&v,   g_v);
    cudaGetSymbolAddress((void**)&ctx, g_ctx);

    rmsnorm_kernel<<<NROWS, 256>>>(x, rmsw);

    gemm_tf32<<<dim3(NDIM/64, NROWS/128), 256>>>(xn, Wq, nullptr, q, NDIM, NDIM);
    gemm_tf32<<<dim3(1,       NROWS/128), 256>>>(xn, Wk, nullptr, k, QD,   NDIM);
    gemm_tf32<<<dim3(2,       NROWS/128), 256>>>(xn, Wv, bv,      v, VDm,  NDIM);

    rope_kernel<<<(NROWS*17 + 7)/8, 256>>>();

    attn_kernel<<<dim3(NS/64, NH, NB), 128>>>(ab);

    gemm_tf32<<<dim3(NDIM/64, NROWS/128), 256>>>(ctx, Wo, bo, out, NDIM, NHV);
}

// round 4
// speedup vs baseline: 1.0008x; 1.0008x over previous
#include <cuda_runtime.h>
#include <cuda_bf16.h>
#include <cstdint>
#include <math.h>

#define NB   2
#define NS   2048
#define NDIM 1024
#define NH   16
#define QD   64
#define VDm  96
#define NHV  (NH*VDm)     /* 1536 */
#define NROWS (NB*NS)     /* 4096 */

// ---------------- scratch (device globals; allocation is forbidden) ----------
__device__ float g_xn [NROWS*NDIM];
__device__ float g_q  [NROWS*NDIM];   // [row][h*64+d]
__device__ float g_k  [NROWS*QD];
__device__ float g_v  [NROWS*VDm];
__device__ float g_ctx[NROWS*NHV];

// ---------------- helpers ----------------------------------------------------
__device__ __forceinline__ uint32_t f2tf(float x){
    uint32_t u; asm("cvt.rna.tf32.f32 %0, %1;" : "=r"(u) : "f"(x)); return u;
}
__device__ __forceinline__ float f2tff(float x){ return __uint_as_float(f2tf(x)); }

__device__ __forceinline__ void mma8(float c[4], const uint32_t a[4], const uint32_t b[2]){
    asm volatile("mma.sync.aligned.m16n8k8.row.col.f32.tf32.tf32.f32 "
        "{%0,%1,%2,%3}, {%4,%5,%6,%7}, {%8,%9}, {%0,%1,%2,%3};"
        : "+f"(c[0]), "+f"(c[1]), "+f"(c[2]), "+f"(c[3])
        : "r"(a[0]), "r"(a[1]), "r"(a[2]), "r"(a[3]), "r"(b[0]), "r"(b[1]));
}

// exp(5*tanh(l/5)) / e^5  (constant e^5 cancels in the softmax normalization)
__device__ __forceinline__ float softcap_exp(float l){
    float e = __expf(0.4f * l);
    return __expf(-10.0f / (1.0f + e));
}

// ---------------- RMSNorm -----------------------------------------------------
__global__ __launch_bounds__(256) void rmsnorm_kernel(const float* __restrict__ x,
                                                      const float* __restrict__ w){
    int row = blockIdx.x;
    int t = threadIdx.x;
    float4 v = ((const float4*)(x + (size_t)row*NDIM))[t];
    float ss = v.x*v.x + v.y*v.y + v.z*v.z + v.w*v.w;
    #pragma unroll
    for (int o=16;o;o>>=1) ss += __shfl_xor_sync(0xffffffffu, ss, o);
    __shared__ float red[8];
    if ((t&31)==0) red[t>>5] = ss;
    __syncthreads();
    if (t < 32){
        float s2 = (t < 8) ? red[t] : 0.f;
        #pragma unroll
        for (int o=4;o;o>>=1) s2 += __shfl_xor_sync(0xffffffffu, s2, o);
        if (t==0) red[0] = s2;
    }
    __syncthreads();
    float scale = rsqrtf(red[0]*(1.0f/NDIM) + 1e-8f);
    float4 wv = ((const float4*)w)[t];
    float4 o;
    o.x = v.x*wv.x*scale; o.y = v.y*wv.y*scale;
    o.z = v.z*wv.z*scale; o.w = v.w*wv.w*scale;
    ((float4*)(g_xn + (size_t)row*NDIM))[t] = o;
}

// ---------------- generic tf32 GEMM: C[M,N] = A[M,K] @ W[K,N] (+bias) ---------
// BM=128, BN=64, BK=16. 256 threads = 8 warps in 4(m) x 2(n), warp tile 32x32.
__global__ __launch_bounds__(256) void gemm_tf32(
    const float* __restrict__ A, const float* __restrict__ W,
    const float* __restrict__ bias, float* __restrict__ C,
    int N, int K)
{
    __shared__ float As[128][20];
    __shared__ float Bs[16][72];
    const int tid = threadIdx.x;
    const int warp = tid>>5, lane = tid&31;
    const int gid = lane>>2, tig = lane&3;
    const int mw = warp>>1, nw = warp&1;
    const int m0 = blockIdx.y*128, n0 = blockIdx.x*64;

    float acc[2][4][4];
    #pragma unroll
    for (int i=0;i<2;i++)
        #pragma unroll
        for (int j=0;j<4;j++)
            #pragma unroll
            for (int l=0;l<4;l++) acc[i][j][l] = 0.f;

    for (int k0=0;k0<K;k0+=16){
        #pragma unroll
        for (int r=0;r<2;r++){
            int f = tid + 256*r;
            int m = f>>2, kq = (f&3)*4;
            float4 v = *(const float4*)(A + (size_t)(m0+m)*K + k0 + kq);
            v.x=f2tff(v.x); v.y=f2tff(v.y); v.z=f2tff(v.z); v.w=f2tff(v.w);
            *(float4*)&As[m][kq] = v;
        }
        {
            int kk = tid>>4, nq = (tid&15)*4;
            float4 v = make_float4(0.f,0.f,0.f,0.f);
            if (n0 + nq + 3 < N){
                v = *(const float4*)(W + (size_t)(k0+kk)*N + n0 + nq);
                v.x=f2tff(v.x); v.y=f2tff(v.y); v.z=f2tff(v.z); v.w=f2tff(v.w);
            }
            *(float4*)&Bs[kk][nq] = v;
        }
        __syncthreads();
        #pragma unroll
        for (int ks=0;ks<2;ks++){
            uint32_t a[2][4];
            #pragma unroll
            for (int mt=0;mt<2;mt++){
                int rb = mw*32 + mt*16;
                a[mt][0] = __float_as_uint(As[rb+gid  ][ks*8+tig  ]);
                a[mt][1] = __float_as_uint(As[rb+gid+8][ks*8+tig  ]);
                a[mt][2] = __float_as_uint(As[rb+gid  ][ks*8+tig+4]);
                a[mt][3] = __float_as_uint(As[rb+gid+8][ks*8+tig+4]);
            }
            #pragma unroll
            for (int nt=0;nt<4;nt++){
                uint32_t bb[2];
                int cc = nw*32 + nt*8 + gid;
                bb[0] = __float_as_uint(Bs[ks*8+tig  ][cc]);
                bb[1] = __float_as_uint(Bs[ks*8+tig+4][cc]);
                #pragma unroll
                for (int mt=0;mt<2;mt++) mma8(acc[mt][nt], a[mt], bb);
            }
        }
        __syncthreads();
    }
    #pragma unroll
    for (int mt=0;mt<2;mt++){
        #pragma unroll
        for (int nt=0;nt<4;nt++){
            int r0 = m0 + mw*32 + mt*16 + gid;
            int c0 = n0 + nw*32 + nt*8 + 2*tig;
            if (c0 + 1 < N || c0 < N){
                float b0 = bias ? bias[c0]   : 0.f;
                float b1 = bias ? bias[c0+1] : 0.f;
                C[(size_t)r0*N + c0]       = acc[mt][nt][0] + b0;
                C[(size_t)r0*N + c0+1]     = acc[mt][nt][1] + b1;
                C[(size_t)(r0+8)*N + c0]   = acc[mt][nt][2] + b0;
                C[(size_t)(r0+8)*N + c0+1] = acc[mt][nt][3] + b1;
            }
        }
    }
}

// ---------------- RoPE (in-place on g_q and g_k) ------------------------------
// One warp per (row, unit). unit 0..15 = q heads, unit 16 = k.
__global__ __launch_bounds__(256) void rope_kernel(){
    int w = threadIdx.x >> 5;
    int lane = threadIdx.x & 31;
    int g = blockIdx.x*8 + w;
    if (g >= NROWS*17) return;
    int row = g / 17;
    int unit = g % 17;
    int s = row % NS;
    float* base = (unit < 16) ? (g_q + (size_t)row*NDIM + unit*QD)
                              : (g_k + (size_t)row*QD);
    const float STEP = 0.106817095236f;   // log10(2048)/31
    float freq = exp10f(-(float)lane * STEP);
    float theta = (float)s * freq;
    float st, ct;
    sincosf(theta, &st, &ct);
    float x1 = base[2*lane];
    float x2 = base[2*lane+1];
    __syncwarp();
    base[lane]      = x1*ct - x2*st;
    base[lane + 32] = x1*st + x2*ct;
}

// ---------------- fused attention ---------------------------------------------
// Block: 64 queries for one (b,h). 128 threads = 4 warps, each owns 16 rows.
// Loop over j in chunks of 32. QK^T in 3xTF32; bias add; softcap-exp (no max
// needed); P -> smem (tf32); P@V single tf32; normalize at the end.
__global__ __launch_bounds__(128) void attn_kernel(const float* __restrict__ bias){
    __shared__ float Khi[32][68];
    __shared__ float Klo[32][68];
    __shared__ float Vs [32][104];
    __shared__ float Ps [64][36];

    const int w = threadIdx.x >> 5, lane = threadIdx.x & 31;
    const int gid = lane >> 2, tig = lane & 3;
    const int it = blockIdx.x;    // 0..31
    const int h  = blockIdx.y;    // 0..15
    const int b  = blockIdx.z;    // 0..1
    const int i0 = it*64;
    const int row0 = b*NS + i0 + w*16;

    // Q fragments (hi/lo split), loop-invariant across j-chunks
    uint32_t qhi[8][4], qlo[8][4];
    #pragma unroll
    for (int ks=0; ks<8; ks++){
        #pragma unroll
        for (int r=0;r<4;r++){
            int rr = gid + (r&1)*8;
            int cc = ks*8 + tig + (r>>1)*4;
            float x = g_q[(size_t)(row0+rr)*NDIM + h*QD + cc];
            uint32_t hi = f2tf(x);
            qhi[ks][r] = hi;
            qlo[ks][r] = f2tf(x - __uint_as_float(hi));
        }
    }

    float ctx[12][4];
    #pragma unroll
    for (int nt=0;nt<12;nt++)
        #pragma unroll
        for (int r=0;r<4;r++) ctx[nt][r] = 0.f;
    float rsum0 = 0.f, rsum1 = 0.f;

    const float* bptr = bias + (((size_t)(b*NH + h))*NS + i0)*NS;

    for (int jc=0; jc<NS/32; jc++){
        int j0 = jc*32;
        __syncthreads();   // previous chunk's smem reads done

        // load K chunk (hi/lo) : 32 x 64
        for (int u = threadIdx.x; u < 32*16; u += 128){
            int jj = u >> 4, c4 = (u & 15)*4;
            float4 v = *(const float4*)(g_k + (size_t)(b*NS + j0 + jj)*QD + c4);
            float h0=f2tff(v.x), h1=f2tff(v.y), h2=f2tff(v.z), h3=f2tff(v.w);
            Khi[jj][c4]=h0; Khi[jj][c4+1]=h1; Khi[jj][c4+2]=h2; Khi[jj][c4+3]=h3;
            Klo[jj][c4]  =f2tff(v.x-h0); Klo[jj][c4+1]=f2tff(v.y-h1);
            Klo[jj][c4+2]=f2tff(v.z-h2); Klo[jj][c4+3]=f2tff(v.w-h3);
        }
        // load V chunk : 32 x 96
        for (int u = threadIdx.x; u < 32*24; u += 128){
            int jj = u / 24, c4 = (u % 24)*4;
            float4 v = *(const float4*)(g_v + (size_t)(b*NS + j0 + jj)*VDm + c4);
            Vs[jj][c4]=f2tff(v.x); Vs[jj][c4+1]=f2tff(v.y);
            Vs[jj][c4+2]=f2tff(v.z); Vs[jj][c4+3]=f2tff(v.w);
        }
        __syncthreads();

        // S = Q @ K^T (16 x 32 per warp), 3xTF32
        float s[4][4];
        #pragma unroll
        for (int nt=0;nt<4;nt++)
            #pragma unroll
            for (int r=0;r<4;r++) s[nt][r]=0.f;
        #pragma unroll
        for (int ks=0;ks<8;ks++){
            #pragma unroll
            for (int nt=0;nt<4;nt++){
                int jj = nt*8 + gid;
                uint32_t bhi[2], blo[2];
                bhi[0] = __float_as_uint(Khi[jj][ks*8+tig  ]);
                bhi[1] = __float_as_uint(Khi[jj][ks*8+tig+4]);
                blo[0] = __float_as_uint(Klo[jj][ks*8+tig  ]);
                blo[1] = __float_as_uint(Klo[jj][ks*8+tig+4]);
                mma8(s[nt], qhi[ks], bhi);
                mma8(s[nt], qhi[ks], blo);
                mma8(s[nt], qlo[ks], bhi);
            }
        }

        // bias + softcap-exp + row-sum + stage P
        int pr = w*16 + gid;
        #pragma unroll
        for (int nt=0;nt<4;nt++){
            int jl = nt*8 + 2*tig;
            const float* bp0 = bptr + (size_t)(w*16+gid)*NS + j0 + jl;
            float2 b0 = *(const float2*)bp0;
            float2 b1 = *(const float2*)(bp0 + (size_t)8*NS);
            float p00 = softcap_exp(s[nt][0] + b0.x);
            float p01 = softcap_exp(s[nt][1] + b0.y);
            float p10 = softcap_exp(s[nt][2] + b1.x);
            float p11 = softcap_exp(s[nt][3] + b1.y);
            rsum0 += p00 + p01;
            rsum1 += p10 + p11;
            Ps[pr  ][jl] = f2tff(p00);  Ps[pr  ][jl+1] = f2tff(p01);
            Ps[pr+8][jl] = f2tff(p10);  Ps[pr+8][jl+1] = f2tff(p11);
        }
        __syncwarp();

        // ctx += P @ V  (16 x 96 per warp)
        #pragma unroll
        for (int ks=0;ks<4;ks++){
            uint32_t pa[4];
            pa[0] = __float_as_uint(Ps[pr  ][ks*8+tig  ]);
            pa[1] = __float_as_uint(Ps[pr+8][ks*8+tig  ]);
            pa[2] = __float_as_uint(Ps[pr  ][ks*8+tig+4]);
            pa[3] = __float_as_uint(Ps[pr+8][ks*8+tig+4]);
            #pragma unroll
            for (int nt=0;nt<12;nt++){
                uint32_t vb[2];
                vb[0] = __float_as_uint(Vs[ks*8+tig  ][nt*8+gid]);
                vb[1] = __float_as_uint(Vs[ks*8+tig+4][nt*8+gid]);
                mma8(ctx[nt], pa, vb);
            }
        }
        __syncwarp();
    }

    // reduce row sums across the quad (tig lanes)
    rsum0 += __shfl_xor_sync(0xffffffffu, rsum0, 1);
    rsum0 += __shfl_xor_sync(0xffffffffu, rsum0, 2);
    rsum1 += __shfl_xor_sync(0xffffffffu, rsum1, 1);
    rsum1 += __shfl_xor_sync(0xffffffffu, rsum1, 2);
    float inv0 = 1.f / rsum0, inv1 = 1.f / rsum1;

    int orow = b*NS + i0 + w*16 + gid;
    #pragma unroll
    for (int nt=0;nt<12;nt++){
        int col = h*VDm + nt*8 + 2*tig;
        g_ctx[(size_t)orow*NHV + col]       = ctx[nt][0]*inv0;
        g_ctx[(size_t)orow*NHV + col+1]     = ctx[nt][1]*inv0;
        g_ctx[(size_t)(orow+8)*NHV + col]   = ctx[nt][2]*inv1;
        g_ctx[(size_t)(orow+8)*NHV + col+1] = ctx[nt][3]*inv1;
    }
}

// ---------------- launch --------------------------------------------------------
extern "C" void kernel_launch(void* const* d_in, const int* in_sizes, int n_in,
                              void* d_out, int out_size) {
    const float* x    = (const float*)d_in[0];
    const float* ab   = (const float*)d_in[1];
    const float* rmsw = (const float*)d_in[2];
    const float* Wq   = (const float*)d_in[3];
    const float* Wk   = (const float*)d_in[4];
    const float* Wv   = (const float*)d_in[5];
    const float* bv   = (const float*)d_in[6];
    const float* Wo   = (const float*)d_in[7];
    const float* bo   = (const float*)d_in[8];
    float* out = (float*)d_out;

    float *xn, *q, *k, *v, *ctx;
    cudaGetSymbolAddress((void**)&xn,  g_xn);
    cudaGetSymbolAddress((void**)&q,   g_q);
    cudaGetSymbolAddress((void**)&k,   g_k);
    cudaGetSymbolAddress((void**)&v,   g_v);
    cudaGetSymbolAddress((void**)&ctx, g_ctx);

    rmsnorm_kernel<<<NROWS, 256>>>(x, rmsw);

    gemm_tf32<<<dim3(NDIM/64, NROWS/128), 256>>>(xn, Wq, nullptr, q, NDIM, NDIM);
    gemm_tf32<<<dim3(1,       NROWS/128), 256>>>(xn, Wk, nullptr, k, QD,   NDIM);
    gemm_tf32<<<dim3(2,       NROWS/128), 256>>>(xn, Wv, bv,      v, VDm,  NDIM);

    rope_kernel<<<(NROWS*17 + 7)/8, 256>>>();

    attn_kernel<<<dim3(NS/64, NH, NB), 128>>>(ab);

    gemm_tf32<<<dim3(NDIM/64, NROWS/128), 256>>>(ctx, Wo, bo, out, NDIM, NHV);
}

// round 5
// speedup vs baseline: 2.7107x; 2.7086x over previous
#include <cuda_runtime.h>
#include <cuda_fp16.h>
#include <cstdint>
#include <math.h>

#define NB 2
#define NS 2048
#define NDIM 1024
#define NH 16
#define QD 64
#define VDm 96
#define NHV (NH*VDm)
#define NROWS (NB*NS)
#define WLD 1216

__device__ __half g_xn [NROWS*NDIM];
__device__ __half g_qh [NROWS*NDIM];
__device__ __half g_ql [NROWS*NDIM];
__device__ __half g_kh [NROWS*QD];
__device__ __half g_kl [NROWS*QD];
__device__ __half g_vt [VDm*NROWS];
__device__ __half g_ctx[NROWS*NHV];
__device__ __half g_wqkv[NDIM*WLD];
__device__ __half g_wo [NHV*NDIM];

__device__ __forceinline__ uint32_t smem_u32(const void* p){
    return (uint32_t)__cvta_generic_to_shared(p);
}
__device__ __forceinline__ void mma16(float c[4], const uint32_t a[4], const uint32_t b[2]){
    asm volatile("mma.sync.aligned.m16n8k16.row.col.f32.f16.f16.f32 "
        "{%0,%1,%2,%3}, {%4,%5,%6,%7}, {%8,%9}, {%0,%1,%2,%3};"
        : "+f"(c[0]), "+f"(c[1]), "+f"(c[2]), "+f"(c[3])
        : "r"(a[0]), "r"(a[1]), "r"(a[2]), "r"(a[3]), "r"(b[0]), "r"(b[1]));
}
__device__ __forceinline__ void ldsm4(uint32_t r[4], uint32_t a){
    asm volatile("ldmatrix.sync.aligned.m8n8.x4.shared.b16 {%0,%1,%2,%3}, [%4];"
        : "=r"(r[0]), "=r"(r[1]), "=r"(r[2]), "=r"(r[3]) : "r"(a));
}
__device__ __forceinline__ void ldsm4t(uint32_t r[4], uint32_t a){
    asm volatile("ldmatrix.sync.aligned.m8n8.x4.trans.shared.b16 {%0,%1,%2,%3}, [%4];"
        : "=r"(r[0]), "=r"(r[1]), "=r"(r[2]), "=r"(r[3]) : "r"(a));
}
__device__ __forceinline__ void cpa(uint32_t dst, const void* src){
    asm volatile("cp.async.cg.shared.global [%0], [%1], 16;" :: "r"(dst), "l"(src) : "memory");
}
#define CP_COMMIT() asm volatile("cp.async.commit_group;" ::: "memory")
#define CP_WAIT0()  asm volatile("cp.async.wait_group 0;" ::: "memory")

__device__ __forceinline__ float softcap_exp(float z){
    float e = __expf(0.4f * z);
    return __expf(-10.0f / (1.0f + e));
}

__global__ __launch_bounds__(256) void rmsnorm_kernel(const float* __restrict__ x,
                                                      const float* __restrict__ w){
    int row = blockIdx.x, t = threadIdx.x;
    float4 v = ((const float4*)(x + (size_t)row*NDIM))[t];
    float ss = v.x*v.x + v.y*v.y + v.z*v.z + v.w*v.w;
    #pragma unroll
    for (int o=16;o;o>>=1) ss += __shfl_xor_sync(0xffffffffu, ss, o);
    __shared__ float red[8];
    if ((t&31)==0) red[t>>5] = ss;
    __syncthreads();
    if (t < 32){
        float s2 = (t < 8) ? red[t] : 0.f;
        #pragma unroll
        for (int o=4;o;o>>=1) s2 += __shfl_xor_sync(0xffffffffu, s2, o);
        if (t==0) red[0] = s2;
    }
    __syncthreads();
    float sc = rsqrtf(red[0]*(1.0f/NDIM) + 1e-8f);
    float4 wv = ((const float4*)w)[t];
    __half2* dst = (__half2*)(g_xn + (size_t)row*NDIM);
    dst[2*t]   = __floats2half2_rn(v.x*wv.x*sc, v.y*wv.y*sc);
    dst[2*t+1] = __floats2half2_rn(v.z*wv.z*sc, v.w*wv.w*sc);
}

__global__ void pack_wqkv(const float* __restrict__ Wq, const float* __restrict__ Wk,
                          const float* __restrict__ Wv){
    int row = blockIdx.y, col = blockIdx.x*256 + threadIdx.x;
    if (col >= WLD) return;
    float v = 0.f;
    if (col < 1024)      v = Wq[(size_t)row*1024 + col];
    else if (col < 1088) v = Wk[(size_t)row*64 + col-1024];
    else if (col < 1184) v = Wv[(size_t)row*96 + col-1088];
    g_wqkv[(size_t)row*WLD + col] = __float2half_rn(v);
}
__global__ void conv_wo(const float* __restrict__ Wo){
    int i = blockIdx.x*256 + threadIdx.x;
    g_wo[i] = __float2half_rn(Wo[i]);
}

// fp16 GEMM: BM=128,BN=64,BK=32; 256 thr, warps 4(m)x2(n).
// MODE 0: C=A@W+bias (fp32). MODE 1: fused QKV epilogue (rope / vt).
template<int MODE>
__global__ __launch_bounds__(256) void gemm_f16(
    const __half* __restrict__ A, int lda, const __half* __restrict__ W, int ldw,
    const float* __restrict__ bias, float* __restrict__ C, int NIT)
{
    __shared__ __align__(16) __half sm[2*7424];  // A 128x40 + B 32x72 per stage
    const int tid = threadIdx.x, warp = tid>>5, lane = tid&31;
    const int gid = lane>>2, tig = lane&3, mw = warp>>1, nw = warp&1;
    const int m0 = blockIdx.y*128, n0 = blockIdx.x*64;

    float acc[2][4][4];
    #pragma unroll
    for (int i=0;i<2;i++)
        #pragma unroll
        for (int j=0;j<4;j++)
            #pragma unroll
            for (int l=0;l<4;l++) acc[i][j][l]=0.f;

    {
        uint32_t ab = smem_u32(sm), bb2 = ab + 5120*2;
        #pragma unroll
        for (int i=0;i<2;i++){
            int idx = tid + 256*i, r = idx>>2, s = idx&3;
            cpa(ab + (r*40+s*8)*2, A + (size_t)(m0+r)*lda + s*8);
        }
        { int r = tid>>3, s = tid&7; cpa(bb2 + (r*72+s*8)*2, W + (size_t)r*ldw + n0 + s*8); }
        CP_COMMIT();
    }
    for (int it=0; it<NIT; it++){
        CP_WAIT0();
        __syncthreads();
        if (it+1 < NIT){
            int st = (it+1)&1, k0 = (it+1)*32;
            uint32_t ab = smem_u32(sm + st*7424), bb2 = ab + 5120*2;
            #pragma unroll
            for (int i=0;i<2;i++){
                int idx = tid + 256*i, r = idx>>2, s = idx&3;
                cpa(ab + (r*40+s*8)*2, A + (size_t)(m0+r)*lda + k0 + s*8);
            }
            { int r = tid>>3, s = tid&7; cpa(bb2 + (r*72+s*8)*2, W + (size_t)(k0+r)*ldw + n0 + s*8); }
            CP_COMMIT();
        }
        uint32_t abase = smem_u32(sm + (it&1)*7424), bbase = abase + 5120*2;
        uint32_t aa[2][2][4], bb[4][4];
        #pragma unroll
        for (int mt=0;mt<2;mt++)
            #pragma unroll
            for (int ks=0;ks<2;ks++){
                int r = mw*32 + mt*16 + (lane&15), c = ks*16 + ((lane>>4)<<3);
                ldsm4(aa[mt][ks], abase + (r*40+c)*2);
            }
        #pragma unroll
        for (int nt=0;nt<4;nt++)
            ldsm4t(bb[nt], bbase + (lane*72 + nw*32 + nt*8)*2);
        #pragma unroll
        for (int ks=0;ks<2;ks++)
            #pragma unroll
            for (int nt=0;nt<4;nt++)
                #pragma unroll
                for (int mt=0;mt<2;mt++)
                    mma16(acc[mt][nt], aa[mt][ks], &bb[nt][ks*2]);
    }

    if (MODE == 0){
        #pragma unroll
        for (int mt=0;mt<2;mt++)
            #pragma unroll
            for (int nt=0;nt<4;nt++){
                int r0 = m0 + mw*32 + mt*16 + gid, c0 = n0 + nw*32 + nt*8 + 2*tig;
                float b0 = bias[c0], b1 = bias[c0+1];
                C[(size_t)r0*NDIM + c0]       = acc[mt][nt][0] + b0;
                C[(size_t)r0*NDIM + c0+1]     = acc[mt][nt][1] + b1;
                C[(size_t)(r0+8)*NDIM + c0]   = acc[mt][nt][2] + b0;
                C[(size_t)(r0+8)*NDIM + c0+1] = acc[mt][nt][3] + b1;
            }
    } else {
        int t = blockIdx.x;  // 0..15 Q heads, 16 K, 17..18 V
        #pragma unroll
        for (int mt=0;mt<2;mt++)
            #pragma unroll
            for (int nt=0;nt<4;nt++){
                int r0 = m0 + mw*32 + mt*16 + gid, c0 = nw*32 + nt*8 + 2*tig;
                if (t <= 16){
                    int d = c0 >> 1;
                    float freq = exp2f(-(float)d * (11.0f/31.0f));
                    #pragma unroll
                    for (int rr=0;rr<2;rr++){
                        int row = r0 + rr*8;
                        float x1 = acc[mt][nt][rr*2], x2 = acc[mt][nt][rr*2+1];
                        float st, ct;
                        sincosf((float)(row & (NS-1)) * freq, &st, &ct);
                        float o1 = x1*ct - x2*st, o2 = x1*st + x2*ct;
                        __half h1 = __float2half_rn(o1), h2 = __float2half_rn(o2);
                        __half l1 = __float2half_rn(o1 - __half2float(h1));
                        __half l2 = __float2half_rn(o2 - __half2float(h2));
                        if (t < 16){
                            size_t base = (size_t)row*NDIM + t*64;
                            g_qh[base+d] = h1; g_ql[base+d] = l1;
                            g_qh[base+d+32] = h2; g_ql[base+d+32] = l2;
                        } else {
                            size_t base = (size_t)row*QD;
                            g_kh[base+d] = h1; g_kl[base+d] = l1;
                            g_kh[base+d+32] = h2; g_kl[base+d+32] = l2;
                        }
                    }
                } else {
                    int vc = (t-17)*64 + c0;
                    if (vc < VDm){
                        float b0 = bias[vc], b1 = bias[vc+1];
                        g_vt[(size_t)vc*NROWS + r0]       = __float2half_rn(acc[mt][nt][0]+b0);
                        g_vt[(size_t)(vc+1)*NROWS + r0]   = __float2half_rn(acc[mt][nt][1]+b1);
                        g_vt[(size_t)vc*NROWS + r0+8]     = __float2half_rn(acc[mt][nt][2]+b0);
                        g_vt[(size_t)(vc+1)*NROWS + r0+8] = __float2half_rn(acc[mt][nt][3]+b1);
                    }
                }
            }
    }
}

// attention: 64 queries x (b,h) per block, 128 thr / 4 warps, j-chunks of 64.
// smem per stage: kh 64x72 + kl 64x72 + vt 96x72 = 16128 halfs; Ps 64x72 after.
__global__ __launch_bounds__(128) void attn_kernel(const float* __restrict__ bias){
    extern __shared__ __align__(16) __half dynsm[];
    const int tid = threadIdx.x, w = tid>>5, lane = tid&31;
    const int gid = lane>>2, tig = lane&3;
    const int i0 = blockIdx.x*64, h = blockIdx.y, b = blockIdx.z;
    const int bNS = b*NS, row0 = bNS + i0 + w*16;
    const uint32_t sm0 = smem_u32(dynsm);

    uint32_t qh[4][4], ql[4][4];
    #pragma unroll
    for (int ks=0;ks<4;ks++){
        size_t base = (size_t)(row0+gid)*NDIM + h*QD + ks*16 + 2*tig;
        size_t base8 = base + (size_t)8*NDIM;
        qh[ks][0] = *(const uint32_t*)(g_qh + base);
        qh[ks][1] = *(const uint32_t*)(g_qh + base8);
        qh[ks][2] = *(const uint32_t*)(g_qh + base + 8);
        qh[ks][3] = *(const uint32_t*)(g_qh + base8 + 8);
        ql[ks][0] = *(const uint32_t*)(g_ql + base);
        ql[ks][1] = *(const uint32_t*)(g_ql + base8);
        ql[ks][2] = *(const uint32_t*)(g_ql + base + 8);
        ql[ks][3] = *(const uint32_t*)(g_ql + base8 + 8);
    }
    float ctx[12][4];
    #pragma unroll
    for (int nt=0;nt<12;nt++)
        #pragma unroll
        for (int r=0;r<4;r++) ctx[nt][r]=0.f;
    float rsum0 = 0.f, rsum1 = 0.f;
    const float* brow = bias + ((size_t)(b*NH+h)*NS + (i0 + w*16 + gid))*NS;

    {
        #pragma unroll
        for (int i=0;i<4;i++){
            int idx = tid + 128*i, r = idx>>3, s = idx&7;
            cpa(sm0 + (r*72+s*8)*2,        g_kh + (size_t)(bNS+r)*QD + s*8);
            cpa(sm0 + (4608 + r*72+s*8)*2, g_kl + (size_t)(bNS+r)*QD + s*8);
        }
        #pragma unroll
        for (int i=0;i<6;i++){
            int idx = tid + 128*i, r = idx>>3, s = idx&7;
            cpa(sm0 + (9216 + r*72+s*8)*2, g_vt + (size_t)r*NROWS + bNS + s*8);
        }
        CP_COMMIT();
    }

    for (int jc=0; jc<NS/64; jc++){
        CP_WAIT0();
        __syncthreads();
        if (jc+1 < NS/64){
            int j0n = (jc+1)*64;
            uint32_t sb = sm0 + ((jc+1)&1)*16128*2;
            #pragma unroll
            for (int i=0;i<4;i++){
                int idx = tid + 128*i, r = idx>>3, s = idx&7;
                cpa(sb + (r*72+s*8)*2,        g_kh + (size_t)(bNS+j0n+r)*QD + s*8);
                cpa(sb + (4608 + r*72+s*8)*2, g_kl + (size_t)(bNS+j0n+r)*QD + s*8);
            }
            #pragma unroll
            for (int i=0;i<6;i++){
                int idx = tid + 128*i, r = idx>>3, s = idx&7;
                cpa(sb + (9216 + r*72+s*8)*2, g_vt + (size_t)r*NROWS + bNS + j0n + s*8);
            }
            CP_COMMIT();
        }
        const int j0 = jc*64;
        uint32_t cb = sm0 + (jc&1)*16128*2;

        float2 bz[8][2];
        #pragma unroll
        for (int nt=0;nt<8;nt++){
            bz[nt][0] = *(const float2*)(brow + j0 + nt*8 + 2*tig);
            bz[nt][1] = *(const float2*)(brow + (size_t)8*NS + j0 + nt*8 + 2*tig);
        }

        float S[8][4];
        #pragma unroll
        for (int nt=0;nt<8;nt++)
            #pragma unroll
            for (int r=0;r<4;r++) S[nt][r]=0.f;
        #pragma unroll
        for (int ks=0;ks<4;ks++){
            #pragma unroll
            for (int jb=0;jb<4;jb++){
                int r = jb*16 + ((lane>>4)<<3) + (lane&7);
                int c = ks*16 + ((lane>>3)&1)*8;
                uint32_t kf[4], lf[4];
                ldsm4(kf, cb + (r*72+c)*2);
                ldsm4(lf, cb + (4608 + r*72+c)*2);
                mma16(S[2*jb],   qh[ks], &kf[0]);
                mma16(S[2*jb+1], qh[ks], &kf[2]);
                mma16(S[2*jb],   qh[ks], &lf[0]);
                mma16(S[2*jb+1], qh[ks], &lf[2]);
                mma16(S[2*jb],   ql[ks], &kf[0]);
                mma16(S[2*jb+1], ql[ks], &kf[2]);
            }
        }

        __half* Ps = dynsm + 32256;
        int pr = w*16 + gid;
        #pragma unroll
        for (int nt=0;nt<8;nt++){
            float p00 = softcap_exp(S[nt][0] + bz[nt][0].x);
            float p01 = softcap_exp(S[nt][1] + bz[nt][0].y);
            float p10 = softcap_exp(S[nt][2] + bz[nt][1].x);
            float p11 = softcap_exp(S[nt][3] + bz[nt][1].y);
            rsum0 += p00 + p01; rsum1 += p10 + p11;
            int cc = nt*8 + 2*tig;
            *(__half2*)(Ps + (size_t)pr*72 + cc)     = __floats2half2_rn(p00, p01);
            *(__half2*)(Ps + (size_t)(pr+8)*72 + cc) = __floats2half2_rn(p10, p11);
        }
        __syncwarp();

        uint32_t psb = sm0 + 32256*2;
        uint32_t pa[4][4];
        #pragma unroll
        for (int ks=0;ks<4;ks++){
            int r = w*16 + (lane&15), c = ks*16 + ((lane>>4)<<3);
            ldsm4(pa[ks], psb + (r*72+c)*2);
        }
        #pragma unroll
        for (int ks=0;ks<4;ks++){
            #pragma unroll
            for (int cbk=0;cbk<6;cbk++){
                int r = cbk*16 + ((lane>>4)<<3) + (lane&7);
                int c = ks*16 + ((lane>>3)&1)*8;
                uint32_t vf[4];
                ldsm4(vf, cb + (9216 + r*72+c)*2);
                mma16(ctx[2*cbk],   pa[ks], &vf[0]);
                mma16(ctx[2*cbk+1], pa[ks], &vf[2]);
            }
        }
    }

    rsum0 += __shfl_xor_sync(0xffffffffu, rsum0, 1);
    rsum0 += __shfl_xor_sync(0xffffffffu, rsum0, 2);
    rsum1 += __shfl_xor_sync(0xffffffffu, rsum1, 1);
    rsum1 += __shfl_xor_sync(0xffffffffu, rsum1, 2);
    float inv0 = 1.f/rsum0, inv1 = 1.f/rsum1;
    int orow = row0 + gid;
    #pragma unroll
    for (int nt=0;nt<12;nt++){
        int col = h*VDm + nt*8 + 2*tig;
        *(__half2*)(g_ctx + (size_t)orow*NHV + col) =
            __floats2half2_rn(ctx[nt][0]*inv0, ctx[nt][1]*inv0);
        *(__half2*)(g_ctx + (size_t)(orow+8)*NHV + col) =
            __floats2half2_rn(ctx[nt][2]*inv1, ctx[nt][3]*inv1);
    }
}

extern "C" void kernel_launch(void* const* d_in, const int* in_sizes, int n_in,
                              void* d_out, int out_size) {
    const float* x    = (const float*)d_in[0];
    const float* ab   = (const float*)d_in[1];
    const float* rmsw = (const float*)d_in[2];
    const float* Wq   = (const float*)d_in[3];
    const float* Wk   = (const float*)d_in[4];
    const float* Wv   = (const float*)d_in[5];
    const float* bv   = (const float*)d_in[6];
    const float* Wo   = (const float*)d_in[7];
    const float* bo   = (const float*)d_in[8];
    float* out = (float*)d_out;

    __half *xn, *ctx, *wqkv, *wo;
    cudaGetSymbolAddress((void**)&xn,   g_xn);
    cudaGetSymbolAddress((void**)&ctx,  g_ctx);
    cudaGetSymbolAddress((void**)&wqkv, g_wqkv);
    cudaGetSymbolAddress((void**)&wo,   g_wo);

    cudaFuncSetAttribute(attn_kernel, cudaFuncAttributeMaxDynamicSharedMemorySize, 73728);

    rmsnorm_kernel<<<NROWS, 256>>>(x, rmsw);
    pack_wqkv<<<dim3(5, NDIM), 256>>>(Wq, Wk, Wv);
    conv_wo<<<(NHV*NDIM)/256, 256>>>(Wo);

    gemm_f16<1><<<dim3(19, NROWS/128), 256>>>(xn, NDIM, wqkv, WLD, bv, nullptr, 32);

    attn_kernel<<<dim3(NS/64, NH, NB), 128, 73728>>>(ab);

    gemm_f16<0><<<dim3(NDIM/64, NROWS/128), 256>>>(ctx, NHV, wo, NDIM, bo, out, 48);
}

// round 6
// speedup vs baseline: 3.4258x; 1.2638x over previous
#include <cuda_runtime.h>
#include <cuda_fp16.h>
#include <cstdint>
#include <math.h>

#define NB 2
#define NS 2048
#define NDIM 1024
#define NH 16
#define QD 64
#define VDm 96
#define NHV (NH*VDm)
#define NROWS (NB*NS)
#define WLD 1216

__device__ __half g_xn [NROWS*NDIM];
__device__ __half g_qh [NROWS*NDIM];
__device__ __half g_ql [NROWS*NDIM];
__device__ __half g_kh [NROWS*QD];
__device__ __half g_vt [VDm*NROWS];
__device__ __half g_ctx[NROWS*NHV];
__device__ __half g_wqkv[NDIM*WLD];
__device__ __half g_wo [NHV*NDIM];

__device__ __forceinline__ uint32_t smem_u32(const void* p){
    return (uint32_t)__cvta_generic_to_shared(p);
}
__device__ __forceinline__ void mma16(float c[4], const uint32_t a[4], const uint32_t b[2]){
    asm volatile("mma.sync.aligned.m16n8k16.row.col.f32.f16.f16.f32 "
        "{%0,%1,%2,%3}, {%4,%5,%6,%7}, {%8,%9}, {%0,%1,%2,%3};"
        : "+f"(c[0]), "+f"(c[1]), "+f"(c[2]), "+f"(c[3])
        : "r"(a[0]), "r"(a[1]), "r"(a[2]), "r"(a[3]), "r"(b[0]), "r"(b[1]));
}
__device__ __forceinline__ void ldsm4(uint32_t r[4], uint32_t a){
    asm volatile("ldmatrix.sync.aligned.m8n8.x4.shared.b16 {%0,%1,%2,%3}, [%4];"
        : "=r"(r[0]), "=r"(r[1]), "=r"(r[2]), "=r"(r[3]) : "r"(a));
}
__device__ __forceinline__ void ldsm4t(uint32_t r[4], uint32_t a){
    asm volatile("ldmatrix.sync.aligned.m8n8.x4.trans.shared.b16 {%0,%1,%2,%3}, [%4];"
        : "=r"(r[0]), "=r"(r[1]), "=r"(r[2]), "=r"(r[3]) : "r"(a));
}
__device__ __forceinline__ void cpa(uint32_t dst, const void* src){
    asm volatile("cp.async.cg.shared.global [%0], [%1], 16;" :: "r"(dst), "l"(src) : "memory");
}
#define CP_COMMIT() asm volatile("cp.async.commit_group;" ::: "memory")
#define CP_WAIT0()  asm volatile("cp.async.wait_group 0;" ::: "memory")
#define CP_WAIT1()  asm volatile("cp.async.wait_group 1;" ::: "memory")

__device__ __forceinline__ uint32_t packh2(float a, float b){
    __half2 h = __floats2half2_rn(a, b);
    return *(uint32_t*)&h;
}
// exp(5*tanh(z/5))/e^5  (e^5 cancels in normalization)
__device__ __forceinline__ float softcap_exp(float z){
    float t; asm("tanh.approx.f32 %0, %1;" : "=f"(t) : "f"(0.2f*z));
    return __expf(5.0f*t - 5.0f);
}

__global__ __launch_bounds__(256) void rmsnorm_kernel(const float* __restrict__ x,
                                                      const float* __restrict__ w){
    int row = blockIdx.x, t = threadIdx.x;
    float4 v = ((const float4*)(x + (size_t)row*NDIM))[t];
    float ss = v.x*v.x + v.y*v.y + v.z*v.z + v.w*v.w;
    #pragma unroll
    for (int o=16;o;o>>=1) ss += __shfl_xor_sync(0xffffffffu, ss, o);
    __shared__ float red[8];
    if ((t&31)==0) red[t>>5] = ss;
    __syncthreads();
    if (t < 32){
        float s2 = (t < 8) ? red[t] : 0.f;
        #pragma unroll
        for (int o=4;o;o>>=1) s2 += __shfl_xor_sync(0xffffffffu, s2, o);
        if (t==0) red[0] = s2;
    }
    __syncthreads();
    float sc = rsqrtf(red[0]*(1.0f/NDIM) + 1e-8f);
    float4 wv = ((const float4*)w)[t];
    __half2* dst = (__half2*)(g_xn + (size_t)row*NDIM);
    dst[2*t]   = __floats2half2_rn(v.x*wv.x*sc, v.y*wv.y*sc);
    dst[2*t+1] = __floats2half2_rn(v.z*wv.z*sc, v.w*wv.w*sc);
}

__global__ void pack_wqkv(const float* __restrict__ Wq, const float* __restrict__ Wk,
                          const float* __restrict__ Wv){
    int row = blockIdx.y, col = blockIdx.x*256 + threadIdx.x;
    if (col >= WLD) return;
    float v = 0.f;
    if (col < 1024)      v = Wq[(size_t)row*1024 + col];
    else if (col < 1088) v = Wk[(size_t)row*64 + col-1024];
    else if (col < 1184) v = Wv[(size_t)row*96 + col-1088];
    g_wqkv[(size_t)row*WLD + col] = __float2half_rn(v);
}
__global__ void conv_wo(const float* __restrict__ Wo){
    int i = blockIdx.x*256 + threadIdx.x;
    g_wo[i] = __float2half_rn(Wo[i]);
}

// fp16 GEMM: BM=128,BN=64,BK=32; 3-stage cp.async pipeline.
// MODE 0: C=A@W+bias (fp32). MODE 1: fused QKV epilogue (rope / vt).
template<int MODE>
__global__ __launch_bounds__(256) void gemm_f16(
    const __half* __restrict__ A, int lda, const __half* __restrict__ W, int ldw,
    const float* __restrict__ bias, float* __restrict__ C, int NIT)
{
    __shared__ __align__(16) __half sm[3*7424];  // stage: A 128x40 + B 32x72
    const int tid = threadIdx.x, warp = tid>>5, lane = tid&31;
    const int gid = lane>>2, tig = lane&3, mw = warp>>1, nw = warp&1;
    const int m0 = blockIdx.y*128, n0 = blockIdx.x*64;

    float acc[2][4][4];
    #pragma unroll
    for (int i=0;i<2;i++)
        #pragma unroll
        for (int j=0;j<4;j++)
            #pragma unroll
            for (int l=0;l<4;l++) acc[i][j][l]=0.f;

    #pragma unroll 1
    for (int p=0;p<2;p++){
        uint32_t ab = smem_u32(sm + p*7424), bb2 = ab + 5120*2;
        int k0 = p*32;
        #pragma unroll
        for (int i=0;i<2;i++){
            int idx = tid + 256*i, r = idx>>2, s = idx&3;
            cpa(ab + (r*40+s*8)*2, A + (size_t)(m0+r)*lda + k0 + s*8);
        }
        { int r = tid>>3, s = tid&7; cpa(bb2 + (r*72+s*8)*2, W + (size_t)(k0+r)*ldw + n0 + s*8); }
        CP_COMMIT();
    }
    for (int it=0; it<NIT; it++){
        CP_WAIT1();
        __syncthreads();
        if (it+2 < NIT){
            int st = (it+2)%3, k0 = (it+2)*32;
            uint32_t ab = smem_u32(sm + st*7424), bb2 = ab + 5120*2;
            #pragma unroll
            for (int i=0;i<2;i++){
                int idx = tid + 256*i, r = idx>>2, s = idx&3;
                cpa(ab + (r*40+s*8)*2, A + (size_t)(m0+r)*lda + k0 + s*8);
            }
            { int r = tid>>3, s = tid&7; cpa(bb2 + (r*72+s*8)*2, W + (size_t)(k0+r)*ldw + n0 + s*8); }
            CP_COMMIT();
        }
        uint32_t abase = smem_u32(sm + (it%3)*7424), bbase = abase + 5120*2;
        uint32_t aa[2][2][4], bb[4][4];
        #pragma unroll
        for (int mt=0;mt<2;mt++)
            #pragma unroll
            for (int ks=0;ks<2;ks++){
                int r = mw*32 + mt*16 + (lane&15), c = ks*16 + ((lane>>4)<<3);
                ldsm4(aa[mt][ks], abase + (r*40+c)*2);
            }
        #pragma unroll
        for (int nt=0;nt<4;nt++)
            ldsm4t(bb[nt], bbase + (lane*72 + nw*32 + nt*8)*2);
        #pragma unroll
        for (int ks=0;ks<2;ks++)
            #pragma unroll
            for (int nt=0;nt<4;nt++)
                #pragma unroll
                for (int mt=0;mt<2;mt++)
                    mma16(acc[mt][nt], aa[mt][ks], &bb[nt][ks*2]);
    }

    if (MODE == 0){
        #pragma unroll
        for (int mt=0;mt<2;mt++)
            #pragma unroll
            for (int nt=0;nt<4;nt++){
                int r0 = m0 + mw*32 + mt*16 + gid, c0 = n0 + nw*32 + nt*8 + 2*tig;
                float b0 = bias[c0], b1 = bias[c0+1];
                C[(size_t)r0*NDIM + c0]       = acc[mt][nt][0] + b0;
                C[(size_t)r0*NDIM + c0+1]     = acc[mt][nt][1] + b1;
                C[(size_t)(r0+8)*NDIM + c0]   = acc[mt][nt][2] + b0;
                C[(size_t)(r0+8)*NDIM + c0+1] = acc[mt][nt][3] + b1;
            }
    } else {
        int t = blockIdx.x;  // 0..15 Q heads, 16 K, 17..18 V
        #pragma unroll
        for (int mt=0;mt<2;mt++)
            #pragma unroll
            for (int nt=0;nt<4;nt++){
                int r0 = m0 + mw*32 + mt*16 + gid, c0 = nw*32 + nt*8 + 2*tig;
                if (t <= 16){
                    int d = c0 >> 1;
                    float freq = exp2f(-(float)d * (11.0f/31.0f));
                    #pragma unroll
                    for (int rr=0;rr<2;rr++){
                        int row = r0 + rr*8;
                        float x1 = acc[mt][nt][rr*2], x2 = acc[mt][nt][rr*2+1];
                        float st, ct;
                        sincosf((float)(row & (NS-1)) * freq, &st, &ct);
                        float o1 = x1*ct - x2*st, o2 = x1*st + x2*ct;
                        __half h1 = __float2half_rn(o1), h2 = __float2half_rn(o2);
                        if (t < 16){
                            size_t base = (size_t)row*NDIM + t*64;
                            g_qh[base+d]    = h1;
                            g_qh[base+d+32] = h2;
                            g_ql[base+d]    = __float2half_rn(o1 - __half2float(h1));
                            g_ql[base+d+32] = __float2half_rn(o2 - __half2float(h2));
                        } else {
                            size_t base = (size_t)row*QD;
                            g_kh[base+d]    = h1;
                            g_kh[base+d+32] = h2;
                        }
                    }
                } else {
                    int vc = (t-17)*64 + c0;
                    if (vc < VDm){
                        float b0 = bias[vc], b1 = bias[vc+1];
                        g_vt[(size_t)vc*NROWS + r0]       = __float2half_rn(acc[mt][nt][0]+b0);
                        g_vt[(size_t)(vc+1)*NROWS + r0]   = __float2half_rn(acc[mt][nt][1]+b1);
                        g_vt[(size_t)vc*NROWS + r0+8]     = __float2half_rn(acc[mt][nt][2]+b0);
                        g_vt[(size_t)(vc+1)*NROWS + r0+8] = __float2half_rn(acc[mt][nt][3]+b1);
                    }
                }
            }
    }
}

// attention: 64 queries x (b,h) per block, 128 thr / 4 warps, j-chunks of 64.
// stage = kh 64x72 + vt 96x72 = 11520 halfs; 2 stages static smem.
__global__ __launch_bounds__(128) void attn_kernel(const float* __restrict__ bias){
    __shared__ __align__(16) __half sm[2*11520];
    const int tid = threadIdx.x, w = tid>>5, lane = tid&31;
    const int gid = lane>>2, tig = lane&3;
    const int i0 = blockIdx.x*64, h = blockIdx.y, b = blockIdx.z;
    const int bNS = b*NS, row0 = bNS + i0 + w*16;
    const uint32_t sm0 = smem_u32(sm);

    uint32_t qh[4][4], ql[4][4];
    #pragma unroll
    for (int ks=0;ks<4;ks++){
        size_t base = (size_t)(row0+gid)*NDIM + h*QD + ks*16 + 2*tig;
        size_t base8 = base + (size_t)8*NDIM;
        qh[ks][0] = *(const uint32_t*)(g_qh + base);
        qh[ks][1] = *(const uint32_t*)(g_qh + base8);
        qh[ks][2] = *(const uint32_t*)(g_qh + base + 8);
        qh[ks][3] = *(const uint32_t*)(g_qh + base8 + 8);
        ql[ks][0] = *(const uint32_t*)(g_ql + base);
        ql[ks][1] = *(const uint32_t*)(g_ql + base8);
        ql[ks][2] = *(const uint32_t*)(g_ql + base + 8);
        ql[ks][3] = *(const uint32_t*)(g_ql + base8 + 8);
    }
    float ctx[12][4];
    #pragma unroll
    for (int nt=0;nt<12;nt++)
        #pragma unroll
        for (int r=0;r<4;r++) ctx[nt][r]=0.f;
    float rsum0 = 0.f, rsum1 = 0.f;
    const float* brow = bias + ((size_t)(b*NH+h)*NS + (i0 + w*16 + gid))*NS;

    {   // stage chunk 0
        #pragma unroll
        for (int i=0;i<4;i++){
            int idx = tid + 128*i, r = idx>>3, s = idx&7;
            cpa(sm0 + (r*72+s*8)*2, g_kh + (size_t)(bNS+r)*QD + s*8);
        }
        #pragma unroll
        for (int i=0;i<6;i++){
            int idx = tid + 128*i, r = idx>>3, s = idx&7;
            cpa(sm0 + (4608 + r*72+s*8)*2, g_vt + (size_t)r*NROWS + bNS + s*8);
        }
        CP_COMMIT();
    }

    for (int jc=0; jc<NS/64; jc++){
        CP_WAIT0();
        __syncthreads();
        if (jc+1 < NS/64){
            int j0n = (jc+1)*64;
            uint32_t sb = sm0 + ((jc+1)&1)*11520*2;
            #pragma unroll
            for (int i=0;i<4;i++){
                int idx = tid + 128*i, r = idx>>3, s = idx&7;
                cpa(sb + (r*72+s*8)*2, g_kh + (size_t)(bNS+j0n+r)*QD + s*8);
            }
            #pragma unroll
            for (int i=0;i<6;i++){
                int idx = tid + 128*i, r = idx>>3, s = idx&7;
                cpa(sb + (4608 + r*72+s*8)*2, g_vt + (size_t)r*NROWS + bNS + j0n + s*8);
            }
            CP_COMMIT();
        }
        const int j0 = jc*64;
        uint32_t cb = sm0 + (jc&1)*11520*2;

        float2 bz[8][2];
        #pragma unroll
        for (int nt=0;nt<8;nt++){
            bz[nt][0] = *(const float2*)(brow + j0 + nt*8 + 2*tig);
            bz[nt][1] = *(const float2*)(brow + (size_t)8*NS + j0 + nt*8 + 2*tig);
        }

        float S[8][4];
        #pragma unroll
        for (int nt=0;nt<8;nt++)
            #pragma unroll
            for (int r=0;r<4;r++) S[nt][r]=0.f;
        #pragma unroll
        for (int ks=0;ks<4;ks++){
            #pragma unroll
            for (int jb=0;jb<4;jb++){
                int r = jb*16 + ((lane>>4)<<3) + (lane&7);
                int c = ks*16 + ((lane>>3)&1)*8;
                uint32_t kf[4];
                ldsm4(kf, cb + (r*72+c)*2);
                mma16(S[2*jb],   qh[ks], &kf[0]);
                mma16(S[2*jb+1], qh[ks], &kf[2]);
                mma16(S[2*jb],   ql[ks], &kf[0]);
                mma16(S[2*jb+1], ql[ks], &kf[2]);
            }
        }

        // softcap-exp; P packed straight into A-fragment registers
        uint32_t pf[8][2];
        #pragma unroll
        for (int nt=0;nt<8;nt++){
            float p00 = softcap_exp(S[nt][0] + bz[nt][0].x);
            float p01 = softcap_exp(S[nt][1] + bz[nt][0].y);
            float p10 = softcap_exp(S[nt][2] + bz[nt][1].x);
            float p11 = softcap_exp(S[nt][3] + bz[nt][1].y);
            rsum0 += p00 + p01; rsum1 += p10 + p11;
            pf[nt][0] = packh2(p00, p01);
            pf[nt][1] = packh2(p10, p11);
        }

        #pragma unroll
        for (int ks=0;ks<4;ks++){
            uint32_t pa[4] = {pf[2*ks][0], pf[2*ks][1], pf[2*ks+1][0], pf[2*ks+1][1]};
            #pragma unroll
            for (int cbk=0;cbk<6;cbk++){
                int r = cbk*16 + ((lane>>4)<<3) + (lane&7);
                int c = ks*16 + ((lane>>3)&1)*8;
                uint32_t vf[4];
                ldsm4(vf, cb + (4608 + r*72+c)*2);
                mma16(ctx[2*cbk],   pa, &vf[0]);
                mma16(ctx[2*cbk+1], pa, &vf[2]);
            }
        }
    }

    rsum0 += __shfl_xor_sync(0xffffffffu, rsum0, 1);
    rsum0 += __shfl_xor_sync(0xffffffffu, rsum0, 2);
    rsum1 += __shfl_xor_sync(0xffffffffu, rsum1, 1);
    rsum1 += __shfl_xor_sync(0xffffffffu, rsum1, 2);
    float inv0 = 1.f/rsum0, inv1 = 1.f/rsum1;
    int orow = row0 + gid;
    #pragma unroll
    for (int nt=0;nt<12;nt++){
        int col = h*VDm + nt*8 + 2*tig;
        *(__half2*)(g_ctx + (size_t)orow*NHV + col) =
            __floats2half2_rn(ctx[nt][0]*inv0, ctx[nt][1]*inv0);
        *(__half2*)(g_ctx + (size_t)(orow+8)*NHV + col) =
            __floats2half2_rn(ctx[nt][2]*inv1, ctx[nt][3]*inv1);
    }
}

extern "C" void kernel_launch(void* const* d_in, const int* in_sizes, int n_in,
                              void* d_out, int out_size) {
    const float* x    = (const float*)d_in[0];
    const float* ab   = (const float*)d_in[1];
    const float* rmsw = (const float*)d_in[2];
    const float* Wq   = (const float*)d_in[3];
    const float* Wk   = (const float*)d_in[4];
    const float* Wv   = (const float*)d_in[5];
    const float* bv   = (const float*)d_in[6];
    const float* Wo   = (const float*)d_in[7];
    const float* bo   = (const float*)d_in[8];
    float* out = (float*)d_out;

    __half *xn, *ctx, *wqkv, *wo;
    cudaGetSymbolAddress((void**)&xn,   g_xn);
    cudaGetSymbolAddress((void**)&ctx,  g_ctx);
    cudaGetSymbolAddress((void**)&wqkv, g_wqkv);
    cudaGetSymbolAddress((void**)&wo,   g_wo);

    rmsnorm_kernel<<<NROWS, 256>>>(x, rmsw);
    pack_wqkv<<<dim3(5, NDIM), 256>>>(Wq, Wk, Wv);
    conv_wo<<<(NHV*NDIM)/256, 256>>>(Wo);

    gemm_f16<1><<<dim3(19, NROWS/128), 256>>>(xn, NDIM, wqkv, WLD, bv, nullptr, 32);

    attn_kernel<<<dim3(NS/64, NH, NB), 128>>>(ab);

    gemm_f16<0><<<dim3(NDIM/64, NROWS/128), 256>>>(ctx, NHV, wo, NDIM, bo, out, 48);
}

// round 9
// speedup vs baseline: 3.4474x; 1.0063x over previous
#include <cuda_runtime.h>
#include <cuda_fp16.h>
#include <cstdint>
#include <math.h>

#define NB 2
#define NS 2048
#define NDIM 1024
#define NH 16
#define QD 64
#define VDm 96
#define NHV (NH*VDm)
#define NROWS (NB*NS)
#define WLD 1216

__device__ __half g_xn [NROWS*NDIM];
__device__ __half g_qh [NROWS*NDIM];
__device__ __half g_ql [NROWS*NDIM];
__device__ __half g_kh [NROWS*QD];
__device__ __half g_vt [VDm*NROWS];
__device__ __half g_ctx[NROWS*NHV];
__device__ __half g_wqkv[NDIM*WLD];
__device__ __half g_wo [NHV*NDIM];

__device__ __forceinline__ uint32_t smem_u32(const void* p){
    return (uint32_t)__cvta_generic_to_shared(p);
}
__device__ __forceinline__ void mma16(float c[4], const uint32_t a[4], const uint32_t b[2]){
    asm volatile("mma.sync.aligned.m16n8k16.row.col.f32.f16.f16.f32 "
        "{%0,%1,%2,%3}, {%4,%5,%6,%7}, {%8,%9}, {%0,%1,%2,%3};"
        : "+f"(c[0]), "+f"(c[1]), "+f"(c[2]), "+f"(c[3])
        : "r"(a[0]), "r"(a[1]), "r"(a[2]), "r"(a[3]), "r"(b[0]), "r"(b[1]));
}
__device__ __forceinline__ void ldsm4(uint32_t r[4], uint32_t a){
    asm volatile("ldmatrix.sync.aligned.m8n8.x4.shared.b16 {%0,%1,%2,%3}, [%4];"
        : "=r"(r[0]), "=r"(r[1]), "=r"(r[2]), "=r"(r[3]) : "r"(a));
}
__device__ __forceinline__ void ldsm4t(uint32_t r[4], uint32_t a){
    asm volatile("ldmatrix.sync.aligned.m8n8.x4.trans.shared.b16 {%0,%1,%2,%3}, [%4];"
        : "=r"(r[0]), "=r"(r[1]), "=r"(r[2]), "=r"(r[3]) : "r"(a));
}
__device__ __forceinline__ void cpa(uint32_t dst, const void* src){
    asm volatile("cp.async.cg.shared.global [%0], [%1], 16;" :: "r"(dst), "l"(src) : "memory");
}
#define CP_COMMIT() asm volatile("cp.async.commit_group;" ::: "memory")
#define CP_WAIT0()  asm volatile("cp.async.wait_group 0;" ::: "memory")
#define CP_WAIT1()  asm volatile("cp.async.wait_group 1;" ::: "memory")

__device__ __forceinline__ uint32_t packh2(float a, float b){
    __half2 h = __floats2half2_rn(a, b);
    return *(uint32_t*)&h;
}
// exp(5*tanh(z/5))/e^5  (e^5 cancels in normalization)
__device__ __forceinline__ float softcap_exp(float z){
    float t; asm("tanh.approx.f32 %0, %1;" : "=f"(t) : "f"(0.2f*z));
    return __expf(5.0f*t - 5.0f);
}

__global__ __launch_bounds__(256) void rmsnorm_kernel(const float* __restrict__ x,
                                                      const float* __restrict__ w){
    int row = blockIdx.x, t = threadIdx.x;
    float4 v = ((const float4*)(x + (size_t)row*NDIM))[t];
    float ss = v.x*v.x + v.y*v.y + v.z*v.z + v.w*v.w;
    #pragma unroll
    for (int o=16;o;o>>=1) ss += __shfl_xor_sync(0xffffffffu, ss, o);
    __shared__ float red[8];
    if ((t&31)==0) red[t>>5] = ss;
    __syncthreads();
    if (t < 32){
        float s2 = (t < 8) ? red[t] : 0.f;
        #pragma unroll
        for (int o=4;o;o>>=1) s2 += __shfl_xor_sync(0xffffffffu, s2, o);
        if (t==0) red[0] = s2;
    }
    __syncthreads();
    float sc = rsqrtf(red[0]*(1.0f/NDIM) + 1e-8f);
    float4 wv = ((const float4*)w)[t];
    __half2* dst = (__half2*)(g_xn + (size_t)row*NDIM);
    dst[2*t]   = __floats2half2_rn(v.x*wv.x*sc, v.y*wv.y*sc);
    dst[2*t+1] = __floats2half2_rn(v.z*wv.z*sc, v.w*wv.w*sc);
}

__global__ void pack_wqkv(const float* __restrict__ Wq, const float* __restrict__ Wk,
                          const float* __restrict__ Wv){
    int row = blockIdx.y, col = blockIdx.x*256 + threadIdx.x;
    if (col >= WLD) return;
    float v = 0.f;
    if (col < 1024)      v = Wq[(size_t)row*1024 + col];
    else if (col < 1088) v = Wk[(size_t)row*64 + col-1024];
    else if (col < 1184) v = Wv[(size_t)row*96 + col-1088];
    g_wqkv[(size_t)row*WLD + col] = __float2half_rn(v);
}
__global__ void conv_wo(const float* __restrict__ Wo){
    int i = blockIdx.x*256 + threadIdx.x;
    g_wo[i] = __float2half_rn(Wo[i]);
}

// fp16 GEMM: BM=128,BN=64,BK=32; 3-stage cp.async pipeline.
// MODE 0: C=A@W+bias (fp32). MODE 1: fused QKV epilogue (rope / vt).
template<int MODE>
__global__ __launch_bounds__(256) void gemm_f16(
    const __half* __restrict__ A, int lda, const __half* __restrict__ W, int ldw,
    const float* __restrict__ bias, float* __restrict__ C, int NIT)
{
    __shared__ __align__(16) __half sm[3*7424];  // stage: A 128x40 + B 32x72
    const int tid = threadIdx.x, warp = tid>>5, lane = tid&31;
    const int gid = lane>>2, tig = lane&3, mw = warp>>1, nw = warp&1;
    const int m0 = blockIdx.y*128, n0 = blockIdx.x*64;

    float acc[2][4][4];
    #pragma unroll
    for (int i=0;i<2;i++)
        #pragma unroll
        for (int j=0;j<4;j++)
            #pragma unroll
            for (int l=0;l<4;l++) acc[i][j][l]=0.f;

    #pragma unroll 1
    for (int p=0;p<2;p++){
        uint32_t ab = smem_u32(sm + p*7424), bb2 = ab + 5120*2;
        int k0 = p*32;
        #pragma unroll
        for (int i=0;i<2;i++){
            int idx = tid + 256*i, r = idx>>2, s = idx&3;
            cpa(ab + (r*40+s*8)*2, A + (size_t)(m0+r)*lda + k0 + s*8);
        }
        { int r = tid>>3, s = tid&7; cpa(bb2 + (r*72+s*8)*2, W + (size_t)(k0+r)*ldw + n0 + s*8); }
        CP_COMMIT();
    }
    for (int it=0; it<NIT; it++){
        CP_WAIT1();
        __syncthreads();
        if (it+2 < NIT){
            int st = (it+2)%3, k0 = (it+2)*32;
            uint32_t ab = smem_u32(sm + st*7424), bb2 = ab + 5120*2;
            #pragma unroll
            for (int i=0;i<2;i++){
                int idx = tid + 256*i, r = idx>>2, s = idx&3;
                cpa(ab + (r*40+s*8)*2, A + (size_t)(m0+r)*lda + k0 + s*8);
            }
            { int r = tid>>3, s = tid&7; cpa(bb2 + (r*72+s*8)*2, W + (size_t)(k0+r)*ldw + n0 + s*8); }
            CP_COMMIT();
        }
        uint32_t abase = smem_u32(sm + (it%3)*7424), bbase = abase + 5120*2;
        uint32_t aa[2][2][4], bb[4][4];
        #pragma unroll
        for (int mt=0;mt<2;mt++)
            #pragma unroll
            for (int ks=0;ks<2;ks++){
                int r = mw*32 + mt*16 + (lane&15), c = ks*16 + ((lane>>4)<<3);
                ldsm4(aa[mt][ks], abase + (r*40+c)*2);
            }
        #pragma unroll
        for (int nt=0;nt<4;nt++)
            ldsm4t(bb[nt], bbase + (lane*72 + nw*32 + nt*8)*2);
        #pragma unroll
        for (int ks=0;ks<2;ks++)
            #pragma unroll
            for (int nt=0;nt<4;nt++)
                #pragma unroll
                for (int mt=0;mt<2;mt++)
                    mma16(acc[mt][nt], aa[mt][ks], &bb[nt][ks*2]);
    }

    if (MODE == 0){
        #pragma unroll
        for (int mt=0;mt<2;mt++)
            #pragma unroll
            for (int nt=0;nt<4;nt++){
                int r0 = m0 + mw*32 + mt*16 + gid, c0 = n0 + nw*32 + nt*8 + 2*tig;
                float b0 = bias[c0], b1 = bias[c0+1];
                C[(size_t)r0*NDIM + c0]       = acc[mt][nt][0] + b0;
                C[(size_t)r0*NDIM + c0+1]     = acc[mt][nt][1] + b1;
                C[(size_t)(r0+8)*NDIM + c0]   = acc[mt][nt][2] + b0;
                C[(size_t)(r0+8)*NDIM + c0+1] = acc[mt][nt][3] + b1;
            }
    } else {
        int t = blockIdx.x;  // 0..15 Q heads, 16 K, 17..18 V
        #pragma unroll
        for (int mt=0;mt<2;mt++)
            #pragma unroll
            for (int nt=0;nt<4;nt++){
                int r0 = m0 + mw*32 + mt*16 + gid, c0 = nw*32 + nt*8 + 2*tig;
                if (t <= 16){
                    int d = c0 >> 1;
                    float freq = exp2f(-(float)d * (11.0f/31.0f));
                    #pragma unroll
                    for (int rr=0;rr<2;rr++){
                        int row = r0 + rr*8;
                        float x1 = acc[mt][nt][rr*2], x2 = acc[mt][nt][rr*2+1];
                        float st, ct;
                        sincosf((float)(row & (NS-1)) * freq, &st, &ct);
                        float o1 = x1*ct - x2*st, o2 = x1*st + x2*ct;
                        __half h1 = __float2half_rn(o1), h2 = __float2half_rn(o2);
                        if (t < 16){
                            size_t base = (size_t)row*NDIM + t*64;
                            g_qh[base+d]    = h1;
                            g_qh[base+d+32] = h2;
                            g_ql[base+d]    = __float2half_rn(o1 - __half2float(h1));
                            g_ql[base+d+32] = __float2half_rn(o2 - __half2float(h2));
                        } else {
                            size_t base = (size_t)row*QD;
                            g_kh[base+d]    = h1;
                            g_kh[base+d+32] = h2;
                        }
                    }
                } else {
                    int vc = (t-17)*64 + c0;
                    if (vc < VDm){
                        float b0 = bias[vc], b1 = bias[vc+1];
                        g_vt[(size_t)vc*NROWS + r0]       = __float2half_rn(acc[mt][nt][0]+b0);
                        g_vt[(size_t)(vc+1)*NROWS + r0]   = __float2half_rn(acc[mt][nt][1]+b1);
                        g_vt[(size_t)vc*NROWS + r0+8]     = __float2half_rn(acc[mt][nt][2]+b0);
                        g_vt[(size_t)(vc+1)*NROWS + r0+8] = __float2half_rn(acc[mt][nt][3]+b1);
                    }
                }
            }
    }
}

// attention: 64 queries x (b,h) per block, 128 thr / 4 warps, j-chunks of 64.
// stage = kh 64x72 + vt 96x72 = 11520 halfs; 2 stages static smem.
__global__ __launch_bounds__(128) void attn_kernel(const float* __restrict__ bias){
    __shared__ __align__(16) __half sm[2*11520];
    const int tid = threadIdx.x, w = tid>>5, lane = tid&31;
    const int gid = lane>>2, tig = lane&3;
    const int i0 = blockIdx.x*64, h = blockIdx.y, b = blockIdx.z;
    const int bNS = b*NS, row0 = bNS + i0 + w*16;
    const uint32_t sm0 = smem_u32(sm);

    uint32_t qh[4][4], ql[4][4];
    #pragma unroll
    for (int ks=0;ks<4;ks++){
        size_t base = (size_t)(row0+gid)*NDIM + h*QD + ks*16 + 2*tig;
        size_t base8 = base + (size_t)8*NDIM;
        qh[ks][0] = *(const uint32_t*)(g_qh + base);
        qh[ks][1] = *(const uint32_t*)(g_qh + base8);
        qh[ks][2] = *(const uint32_t*)(g_qh + base + 8);
        qh[ks][3] = *(const uint32_t*)(g_qh + base8 + 8);
        ql[ks][0] = *(const uint32_t*)(g_ql + base);
        ql[ks][1] = *(const uint32_t*)(g_ql + base8);
        ql[ks][2] = *(const uint32_t*)(g_ql + base + 8);
        ql[ks][3] = *(const uint32_t*)(g_ql + base8 + 8);
    }
    float ctx[12][4];
    #pragma unroll
    for (int nt=0;nt<12;nt++)
        #pragma unroll
        for (int r=0;r<4;r++) ctx[nt][r]=0.f;
    float rsum0 = 0.f, rsum1 = 0.f;
    const float* brow = bias + ((size_t)(b*NH+h)*NS + (i0 + w*16 + gid))*NS;

    {   // stage chunk 0
        #pragma unroll
        for (int i=0;i<4;i++){
            int idx = tid + 128*i, r = idx>>3, s = idx&7;
            cpa(sm0 + (r*72+s*8)*2, g_kh + (size_t)(bNS+r)*QD + s*8);
        }
        #pragma unroll
        for (int i=0;i<6;i++){
            int idx = tid + 128*i, r = idx>>3, s = idx&7;
            cpa(sm0 + (4608 + r*72+s*8)*2, g_vt + (size_t)r*NROWS + bNS + s*8);
        }
        CP_COMMIT();
    }

    for (int jc=0; jc<NS/64; jc++){
        CP_WAIT0();
        __syncthreads();
        if (jc+1 < NS/64){
            int j0n = (jc+1)*64;
            uint32_t sb = sm0 + ((jc+1)&1)*11520*2;
            #pragma unroll
            for (int i=0;i<4;i++){
                int idx = tid + 128*i, r = idx>>3, s = idx&7;
                cpa(sb + (r*72+s*8)*2, g_kh + (size_t)(bNS+j0n+r)*QD + s*8);
            }
            #pragma unroll
            for (int i=0;i<6;i++){
                int idx = tid + 128*i, r = idx>>3, s = idx&7;
                cpa(sb + (4608 + r*72+s*8)*2, g_vt + (size_t)r*NROWS + bNS + j0n + s*8);
            }
            CP_COMMIT();
        }
        const int j0 = jc*64;
        uint32_t cb = sm0 + (jc&1)*11520*2;

        float2 bz[8][2];
        #pragma unroll
        for (int nt=0;nt<8;nt++){
            bz[nt][0] = *(const float2*)(brow + j0 + nt*8 + 2*tig);
            bz[nt][1] = *(const float2*)(brow + (size_t)8*NS + j0 + nt*8 + 2*tig);
        }

        float S[8][4];
        #pragma unroll
        for (int nt=0;nt<8;nt++)
            #pragma unroll
            for (int r=0;r<4;r++) S[nt][r]=0.f;
        #pragma unroll
        for (int ks=0;ks<4;ks++){
            #pragma unroll
            for (int jb=0;jb<4;jb++){
                int r = jb*16 + ((lane>>4)<<3) + (lane&7);
                int c = ks*16 + ((lane>>3)&1)*8;
                uint32_t kf[4];
                ldsm4(kf, cb + (r*72+c)*2);
                mma16(S[2*jb],   qh[ks], &kf[0]);
                mma16(S[2*jb+1], qh[ks], &kf[2]);
                mma16(S[2*jb],   ql[ks], &kf[0]);
                mma16(S[2*jb+1], ql[ks], &kf[2]);
            }
        }

        // softcap-exp; P packed straight into A-fragment registers
        uint32_t pf[8][2];
        #pragma unroll
        for (int nt=0;nt<8;nt++){
            float p00 = softcap_exp(S[nt][0] + bz[nt][0].x);
            float p01 = softcap_exp(S[nt][1] + bz[nt][0].y);
            float p10 = softcap_exp(S[nt][2] + bz[nt][1].x);
            float p11 = softcap_exp(S[nt][3] + bz[nt][1].y);
            rsum0 += p00 + p01; rsum1 += p10 + p11;
            pf[nt][0] = packh2(p00, p01);
            pf[nt][1] = packh2(p10, p11);
        }

        #pragma unroll
        for (int ks=0;ks<4;ks++){
            uint32_t pa[4] = {pf[2*ks][0], pf[2*ks][1], pf[2*ks+1][0], pf[2*ks+1][1]};
            #pragma unroll
            for (int cbk=0;cbk<6;cbk++){
                int r = cbk*16 + ((lane>>4)<<3) + (lane&7);
                int c = ks*16 + ((lane>>3)&1)*8;
                uint32_t vf[4];
                ldsm4(vf, cb + (4608 + r*72+c)*2);
                mma16(ctx[2*cbk],   pa, &vf[0]);
                mma16(ctx[2*cbk+1], pa, &vf[2]);
            }
        }
    }

    rsum0 += __shfl_xor_sync(0xffffffffu, rsum0, 1);
    rsum0 += __shfl_xor_sync(0xffffffffu, rsum0, 2);
    rsum1 += __shfl_xor_sync(0xffffffffu, rsum1, 1);
    rsum1 += __shfl_xor_sync(0xffffffffu, rsum1, 2);
    float inv0 = 1.f/rsum0, inv1 = 1.f/rsum1;
    int orow = row0 + gid;
    #pragma unroll
    for (int nt=0;nt<12;nt++){
        int col = h*VDm + nt*8 + 2*tig;
        *(__half2*)(g_ctx + (size_t)orow*NHV + col) =
            __floats2half2_rn(ctx[nt][0]*inv0, ctx[nt][1]*inv0);
        *(__half2*)(g_ctx + (size_t)(orow+8)*NHV + col) =
            __floats2half2_rn(ctx[nt][2]*inv1, ctx[nt][3]*inv1);
    }
}

extern "C" void kernel_launch(void* const* d_in, const int* in_sizes, int n_in,
                              void* d_out, int out_size) {
    const float* x    = (const float*)d_in[0];
    const float* ab   = (const float*)d_in[1];
    const float* rmsw = (const float*)d_in[2];
    const float* Wq   = (const float*)d_in[3];
    const float* Wk   = (const float*)d_in[4];
    const float* Wv   = (const float*)d_in[5];
    const float* bv   = (const float*)d_in[6];
    const float* Wo   = (const float*)d_in[7];
    const float* bo   = (const float*)d_in[8];
    float* out = (float*)d_out;

    __half *xn, *ctx, *wqkv, *wo;
    cudaGetSymbolAddress((void**)&xn,   g_xn);
    cudaGetSymbolAddress((void**)&ctx,  g_ctx);
    cudaGetSymbolAddress((void**)&wqkv, g_wqkv);
    cudaGetSymbolAddress((void**)&wo,   g_wo);

    rmsnorm_kernel<<<NROWS, 256>>>(x, rmsw);
    pack_wqkv<<<dim3(5, NDIM), 256>>>(Wq, Wk, Wv);
    conv_wo<<<(NHV*NDIM)/256, 256>>>(Wo);

    gemm_f16<1><<<dim3(19, NROWS/128), 256>>>(xn, NDIM, wqkv, WLD, bv, nullptr, 32);

    attn_kernel<<<dim3(NS/64, NH, NB), 128>>>(ab);

    gemm_f16<0><<<dim3(NDIM/64, NROWS/128), 256>>>(ctx, NHV, wo, NDIM, bo, out, 48);
}

// round 11
// speedup vs baseline: 3.4634x; 1.0046x over previous
#include <cuda_runtime.h>
#include <cuda_fp16.h>
#include <cstdint>
#include <math.h>

#define NB 2
#define NS 2048
#define NDIM 1024
#define NH 16
#define QD 64
#define VDm 96
#define NHV (NH*VDm)
#define NROWS (NB*NS)
#define WLD 1216

__device__ __half g_xn [NROWS*NDIM];
__device__ __half g_qh [NROWS*NDIM];
__device__ __half g_ql [NROWS*NDIM];
__device__ __half g_kh [NROWS*QD];
__device__ __half g_vt [VDm*NROWS];
__device__ __half g_ctx[NROWS*NHV];
__device__ __half g_wqkv[NDIM*WLD];
__device__ __half g_wo [NHV*NDIM];

__device__ __forceinline__ uint32_t smem_u32(const void* p){
    return (uint32_t)__cvta_generic_to_shared(p);
}
__device__ __forceinline__ void mma16(float c[4], const uint32_t a[4], const uint32_t b[2]){
    asm volatile("mma.sync.aligned.m16n8k16.row.col.f32.f16.f16.f32 "
        "{%0,%1,%2,%3}, {%4,%5,%6,%7}, {%8,%9}, {%0,%1,%2,%3};"
        : "+f"(c[0]), "+f"(c[1]), "+f"(c[2]), "+f"(c[3])
        : "r"(a[0]), "r"(a[1]), "r"(a[2]), "r"(a[3]), "r"(b[0]), "r"(b[1]));
}
__device__ __forceinline__ void ldsm4(uint32_t r[4], uint32_t a){
    asm volatile("ldmatrix.sync.aligned.m8n8.x4.shared.b16 {%0,%1,%2,%3}, [%4];"
        : "=r"(r[0]), "=r"(r[1]), "=r"(r[2]), "=r"(r[3]) : "r"(a));
}
__device__ __forceinline__ void ldsm4t(uint32_t r[4], uint32_t a){
    asm volatile("ldmatrix.sync.aligned.m8n8.x4.trans.shared.b16 {%0,%1,%2,%3}, [%4];"
        : "=r"(r[0]), "=r"(r[1]), "=r"(r[2]), "=r"(r[3]) : "r"(a));
}
__device__ __forceinline__ void cpa(uint32_t dst, const void* src){
    asm volatile("cp.async.cg.shared.global [%0], [%1], 16;" :: "r"(dst), "l"(src) : "memory");
}
#define CP_COMMIT() asm volatile("cp.async.commit_group;" ::: "memory")
#define CP_WAIT0()  asm volatile("cp.async.wait_group 0;" ::: "memory")
#define CP_WAIT1()  asm volatile("cp.async.wait_group 1;" ::: "memory")

__device__ __forceinline__ uint32_t packh2(float a, float b){
    __half2 h = __floats2half2_rn(a, b);
    return *(uint32_t*)&h;
}
// exp(5*tanh(z/5))/e^5  (e^5 cancels in normalization)
__device__ __forceinline__ float softcap_exp(float z){
    float t; asm("tanh.approx.f32 %0, %1;" : "=f"(t) : "f"(0.2f*z));
    return __expf(5.0f*t - 5.0f);
}

__global__ __launch_bounds__(256) void rmsnorm_kernel(const float* __restrict__ x,
                                                      const float* __restrict__ w){
    int row = blockIdx.x, t = threadIdx.x;
    float4 v = ((const float4*)(x + (size_t)row*NDIM))[t];
    float ss = v.x*v.x + v.y*v.y + v.z*v.z + v.w*v.w;
    #pragma unroll
    for (int o=16;o;o>>=1) ss += __shfl_xor_sync(0xffffffffu, ss, o);
    __shared__ float red[8];
    if ((t&31)==0) red[t>>5] = ss;
    __syncthreads();
    if (t < 32){
        float s2 = (t < 8) ? red[t] : 0.f;
        #pragma unroll
        for (int o=4;o;o>>=1) s2 += __shfl_xor_sync(0xffffffffu, s2, o);
        if (t==0) red[0] = s2;
    }
    __syncthreads();
    float sc = rsqrtf(red[0]*(1.0f/NDIM) + 1e-8f);
    float4 wv = ((const float4*)w)[t];
    __half2* dst = (__half2*)(g_xn + (size_t)row*NDIM);
    dst[2*t]   = __floats2half2_rn(v.x*wv.x*sc, v.y*wv.y*sc);
    dst[2*t+1] = __floats2half2_rn(v.z*wv.z*sc, v.w*wv.w*sc);
}

__global__ void pack_wqkv(const float* __restrict__ Wq, const float* __restrict__ Wk,
                          const float* __restrict__ Wv){
    int row = blockIdx.y, col = blockIdx.x*256 + threadIdx.x;
    if (col >= WLD) return;
    float v = 0.f;
    if (col < 1024)      v = Wq[(size_t)row*1024 + col];
    else if (col < 1088) v = Wk[(size_t)row*64 + col-1024];
    else if (col < 1184) v = Wv[(size_t)row*96 + col-1088];
    g_wqkv[(size_t)row*WLD + col] = __float2half_rn(v);
}
__global__ void conv_wo(const float* __restrict__ Wo){
    int i = blockIdx.x*256 + threadIdx.x;
    g_wo[i] = __float2half_rn(Wo[i]);
}

// fp16 GEMM: BM=128,BN=64,BK=32; 3-stage cp.async pipeline.
// MODE 0: C=A@W+bias (fp32). MODE 1: fused QKV epilogue (rope / vt).
template<int MODE>
__global__ __launch_bounds__(256) void gemm_f16(
    const __half* __restrict__ A, int lda, const __half* __restrict__ W, int ldw,
    const float* __restrict__ bias, float* __restrict__ C, int NIT)
{
    __shared__ __align__(16) __half sm[3*7424];  // stage: A 128x40 + B 32x72
    const int tid = threadIdx.x, warp = tid>>5, lane = tid&31;
    const int gid = lane>>2, tig = lane&3, mw = warp>>1, nw = warp&1;
    const int m0 = blockIdx.y*128, n0 = blockIdx.x*64;

    float acc[2][4][4];
    #pragma unroll
    for (int i=0;i<2;i++)
        #pragma unroll
        for (int j=0;j<4;j++)
            #pragma unroll
            for (int l=0;l<4;l++) acc[i][j][l]=0.f;

    #pragma unroll 1
    for (int p=0;p<2;p++){
        uint32_t ab = smem_u32(sm + p*7424), bb2 = ab + 5120*2;
        int k0 = p*32;
        #pragma unroll
        for (int i=0;i<2;i++){
            int idx = tid + 256*i, r = idx>>2, s = idx&3;
            cpa(ab + (r*40+s*8)*2, A + (size_t)(m0+r)*lda + k0 + s*8);
        }
        { int r = tid>>3, s = tid&7; cpa(bb2 + (r*72+s*8)*2, W + (size_t)(k0+r)*ldw + n0 + s*8); }
        CP_COMMIT();
    }
    for (int it=0; it<NIT; it++){
        CP_WAIT1();
        __syncthreads();
        if (it+2 < NIT){
            int st = (it+2)%3, k0 = (it+2)*32;
            uint32_t ab = smem_u32(sm + st*7424), bb2 = ab + 5120*2;
            #pragma unroll
            for (int i=0;i<2;i++){
                int idx = tid + 256*i, r = idx>>2, s = idx&3;
                cpa(ab + (r*40+s*8)*2, A + (size_t)(m0+r)*lda + k0 + s*8);
            }
            { int r = tid>>3, s = tid&7; cpa(bb2 + (r*72+s*8)*2, W + (size_t)(k0+r)*ldw + n0 + s*8); }
            CP_COMMIT();
        }
        uint32_t abase = smem_u32(sm + (it%3)*7424), bbase = abase + 5120*2;
        uint32_t aa[2][2][4], bb[4][4];
        #pragma unroll
        for (int mt=0;mt<2;mt++)
            #pragma unroll
            for (int ks=0;ks<2;ks++){
                int r = mw*32 + mt*16 + (lane&15), c = ks*16 + ((lane>>4)<<3);
                ldsm4(aa[mt][ks], abase + (r*40+c)*2);
            }
        #pragma unroll
        for (int nt=0;nt<4;nt++)
            ldsm4t(bb[nt], bbase + (lane*72 + nw*32 + nt*8)*2);
        #pragma unroll
        for (int ks=0;ks<2;ks++)
            #pragma unroll
            for (int nt=0;nt<4;nt++)
                #pragma unroll
                for (int mt=0;mt<2;mt++)
                    mma16(acc[mt][nt], aa[mt][ks], &bb[nt][ks*2]);
    }

    if (MODE == 0){
        #pragma unroll
        for (int mt=0;mt<2;mt++)
            #pragma unroll
            for (int nt=0;nt<4;nt++){
                int r0 = m0 + mw*32 + mt*16 + gid, c0 = n0 + nw*32 + nt*8 + 2*tig;
                float b0 = bias[c0], b1 = bias[c0+1];
                C[(size_t)r0*NDIM + c0]       = acc[mt][nt][0] + b0;
                C[(size_t)r0*NDIM + c0+1]     = acc[mt][nt][1] + b1;
                C[(size_t)(r0+8)*NDIM + c0]   = acc[mt][nt][2] + b0;
                C[(size_t)(r0+8)*NDIM + c0+1] = acc[mt][nt][3] + b1;
            }
    } else {
        int t = blockIdx.x;  // 0..15 Q heads, 16 K, 17..18 V
        #pragma unroll
        for (int mt=0;mt<2;mt++)
            #pragma unroll
            for (int nt=0;nt<4;nt++){
                int r0 = m0 + mw*32 + mt*16 + gid, c0 = nw*32 + nt*8 + 2*tig;
                if (t <= 16){
                    int d = c0 >> 1;
                    float freq = exp2f(-(float)d * (11.0f/31.0f));
                    #pragma unroll
                    for (int rr=0;rr<2;rr++){
                        int row = r0 + rr*8;
                        float x1 = acc[mt][nt][rr*2], x2 = acc[mt][nt][rr*2+1];
                        float st, ct;
                        sincosf((float)(row & (NS-1)) * freq, &st, &ct);
                        float o1 = x1*ct - x2*st, o2 = x1*st + x2*ct;
                        __half h1 = __float2half_rn(o1), h2 = __float2half_rn(o2);
                        if (t < 16){
                            size_t base = (size_t)row*NDIM + t*64;
                            g_qh[base+d]    = h1;
                            g_qh[base+d+32] = h2;
                            g_ql[base+d]    = __float2half_rn(o1 - __half2float(h1));
                            g_ql[base+d+32] = __float2half_rn(o2 - __half2float(h2));
                        } else {
                            size_t base = (size_t)row*QD;
                            g_kh[base+d]    = h1;
                            g_kh[base+d+32] = h2;
                        }
                    }
                } else {
                    int vc = (t-17)*64 + c0;
                    if (vc < VDm){
                        float b0 = bias[vc], b1 = bias[vc+1];
                        g_vt[(size_t)vc*NROWS + r0]       = __float2half_rn(acc[mt][nt][0]+b0);
                        g_vt[(size_t)(vc+1)*NROWS + r0]   = __float2half_rn(acc[mt][nt][1]+b1);
                        g_vt[(size_t)vc*NROWS + r0+8]     = __float2half_rn(acc[mt][nt][2]+b0);
                        g_vt[(size_t)(vc+1)*NROWS + r0+8] = __float2half_rn(acc[mt][nt][3]+b1);
                    }
                }
            }
    }
}

// attention: 64 queries x (b,h) per block, 128 thr / 4 warps, j-chunks of 64.
// stage = kh 64x72 + vt 96x72 = 11520 halfs; 2 stages static smem.
__global__ __launch_bounds__(128) void attn_kernel(const float* __restrict__ bias){
    __shared__ __align__(16) __half sm[2*11520];
    const int tid = threadIdx.x, w = tid>>5, lane = tid&31;
    const int gid = lane>>2, tig = lane&3;
    const int i0 = blockIdx.x*64, h = blockIdx.y, b = blockIdx.z;
    const int bNS = b*NS, row0 = bNS + i0 + w*16;
    const uint32_t sm0 = smem_u32(sm);

    uint32_t qh[4][4], ql[4][4];
    #pragma unroll
    for (int ks=0;ks<4;ks++){
        size_t base = (size_t)(row0+gid)*NDIM + h*QD + ks*16 + 2*tig;
        size_t base8 = base + (size_t)8*NDIM;
        qh[ks][0] = *(const uint32_t*)(g_qh + base);
        qh[ks][1] = *(const uint32_t*)(g_qh + base8);
        qh[ks][2] = *(const uint32_t*)(g_qh + base + 8);
        qh[ks][3] = *(const uint32_t*)(g_qh + base8 + 8);
        ql[ks][0] = *(const uint32_t*)(g_ql + base);
        ql[ks][1] = *(const uint32_t*)(g_ql + base8);
        ql[ks][2] = *(const uint32_t*)(g_ql + base + 8);
        ql[ks][3] = *(const uint32_t*)(g_ql + base8 + 8);
    }
    float ctx[12][4];
    #pragma unroll
    for (int nt=0;nt<12;nt++)
        #pragma unroll
        for (int r=0;r<4;r++) ctx[nt][r]=0.f;
    float rsum0 = 0.f, rsum1 = 0.f;
    const float* brow = bias + ((size_t)(b*NH+h)*NS + (i0 + w*16 + gid))*NS;

    {   // stage chunk 0
        #pragma unroll
        for (int i=0;i<4;i++){
            int idx = tid + 128*i, r = idx>>3, s = idx&7;
            cpa(sm0 + (r*72+s*8)*2, g_kh + (size_t)(bNS+r)*QD + s*8);
        }
        #pragma unroll
        for (int i=0;i<6;i++){
            int idx = tid + 128*i, r = idx>>3, s = idx&7;
            cpa(sm0 + (4608 + r*72+s*8)*2, g_vt + (size_t)r*NROWS + bNS + s*8);
        }
        CP_COMMIT();
    }

    for (int jc=0; jc<NS/64; jc++){
        CP_WAIT0();
        __syncthreads();
        if (jc+1 < NS/64){
            int j0n = (jc+1)*64;
            uint32_t sb = sm0 + ((jc+1)&1)*11520*2;
            #pragma unroll
            for (int i=0;i<4;i++){
                int idx = tid + 128*i, r = idx>>3, s = idx&7;
                cpa(sb + (r*72+s*8)*2, g_kh + (size_t)(bNS+j0n+r)*QD + s*8);
            }
            #pragma unroll
            for (int i=0;i<6;i++){
                int idx = tid + 128*i, r = idx>>3, s = idx&7;
                cpa(sb + (4608 + r*72+s*8)*2, g_vt + (size_t)r*NROWS + bNS + j0n + s*8);
            }
            CP_COMMIT();
        }
        const int j0 = jc*64;
        uint32_t cb = sm0 + (jc&1)*11520*2;

        float2 bz[8][2];
        #pragma unroll
        for (int nt=0;nt<8;nt++){
            bz[nt][0] = *(const float2*)(brow + j0 + nt*8 + 2*tig);
            bz[nt][1] = *(const float2*)(brow + (size_t)8*NS + j0 + nt*8 + 2*tig);
        }

        float S[8][4];
        #pragma unroll
        for (int nt=0;nt<8;nt++)
            #pragma unroll
            for (int r=0;r<4;r++) S[nt][r]=0.f;
        #pragma unroll
        for (int ks=0;ks<4;ks++){
            #pragma unroll
            for (int jb=0;jb<4;jb++){
                int r = jb*16 + ((lane>>4)<<3) + (lane&7);
                int c = ks*16 + ((lane>>3)&1)*8;
                uint32_t kf[4];
                ldsm4(kf, cb + (r*72+c)*2);
                mma16(S[2*jb],   qh[ks], &kf[0]);
                mma16(S[2*jb+1], qh[ks], &kf[2]);
                mma16(S[2*jb],   ql[ks], &kf[0]);
                mma16(S[2*jb+1], ql[ks], &kf[2]);
            }
        }

        // softcap-exp; P packed straight into A-fragment registers
        uint32_t pf[8][2];
        #pragma unroll
        for (int nt=0;nt<8;nt++){
            float p00 = softcap_exp(S[nt][0] + bz[nt][0].x);
            float p01 = softcap_exp(S[nt][1] + bz[nt][0].y);
            float p10 = softcap_exp(S[nt][2] + bz[nt][1].x);
            float p11 = softcap_exp(S[nt][3] + bz[nt][1].y);
            rsum0 += p00 + p01; rsum1 += p10 + p11;
            pf[nt][0] = packh2(p00, p01);
            pf[nt][1] = packh2(p10, p11);
        }

        #pragma unroll
        for (int ks=0;ks<4;ks++){
            uint32_t pa[4] = {pf[2*ks][0], pf[2*ks][1], pf[2*ks+1][0], pf[2*ks+1][1]};
            #pragma unroll
            for (int cbk=0;cbk<6;cbk++){
                int r = cbk*16 + ((lane>>4)<<3) + (lane&7);
                int c = ks*16 + ((lane>>3)&1)*8;
                uint32_t vf[4];
                ldsm4(vf, cb + (4608 + r*72+c)*2);
                mma16(ctx[2*cbk],   pa, &vf[0]);
                mma16(ctx[2*cbk+1], pa, &vf[2]);
            }
        }
    }

    rsum0 += __shfl_xor_sync(0xffffffffu, rsum0, 1);
    rsum0 += __shfl_xor_sync(0xffffffffu, rsum0, 2);
    rsum1 += __shfl_xor_sync(0xffffffffu, rsum1, 1);
    rsum1 += __shfl_xor_sync(0xffffffffu, rsum1, 2);
    float inv0 = 1.f/rsum0, inv1 = 1.f/rsum1;
    int orow = row0 + gid;
    #pragma unroll
    for (int nt=0;nt<12;nt++){
        int col = h*VDm + nt*8 + 2*tig;
        *(__half2*)(g_ctx + (size_t)orow*NHV + col) =
            __floats2half2_rn(ctx[nt][0]*inv0, ctx[nt][1]*inv0);
        *(__half2*)(g_ctx + (size_t)(orow+8)*NHV + col) =
            __floats2half2_rn(ctx[nt][2]*inv1, ctx[nt][3]*inv1);
    }
}

extern "C" void kernel_launch(void* const* d_in, const int* in_sizes, int n_in,
                              void* d_out, int out_size) {
    const float* x    = (const float*)d_in[0];
    const float* ab   = (const float*)d_in[1];
    const float* rmsw = (const float*)d_in[2];
    const float* Wq   = (const float*)d_in[3];
    const float* Wk   = (const float*)d_in[4];
    const float* Wv   = (const float*)d_in[5];
    const float* bv   = (const float*)d_in[6];
    const float* Wo   = (const float*)d_in[7];
    const float* bo   = (const float*)d_in[8];
    float* out = (float*)d_out;

    __half *xn, *ctx, *wqkv, *wo;
    cudaGetSymbolAddress((void**)&xn,   g_xn);
    cudaGetSymbolAddress((void**)&ctx,  g_ctx);
    cudaGetSymbolAddress((void**)&wqkv, g_wqkv);
    cudaGetSymbolAddress((void**)&wo,   g_wo);

    rmsnorm_kernel<<<NROWS, 256>>>(x, rmsw);
    pack_wqkv<<<dim3(5, NDIM), 256>>>(Wq, Wk, Wv);
    conv_wo<<<(NHV*NDIM)/256, 256>>>(Wo);

    gemm_f16<1><<<dim3(19, NROWS/128), 256>>>(xn, NDIM, wqkv, WLD, bv, nullptr, 32);

    attn_kernel<<<dim3(NS/64, NH, NB), 128>>>(ab);

    gemm_f16<0><<<dim3(NDIM/64, NROWS/128), 256>>>(ctx, NHV, wo, NDIM, bo, out, 48);
}